// round 10
// baseline (speedup 1.0000x reference)
#include <cuda_runtime.h>
#include <cuda_fp16.h>
#include <cstdint>

#define Bx 16
#define Nx 4096
#define Sx 1024
#define Kx 32
#define Dx 64
#define Px (Bx*Sx*Kx)   // 524288

typedef unsigned long long ull;

// ---------------- device scratch ----------------
__device__ float g_centers[Bx*Sx*3];
__device__ int   g_gidx[Bx*Sx*Kx];
__device__ int   g_prog[Bx];            // fps progress per batch (stale across replays is benign)
__device__ float g_ptsT[Bx*Nx*Dx];
__device__ float g_Y1[64u*Px];          // channel-major
__device__ float g_Y2[64u*Px];          // channel-major
__device__ float g_gmax[Bx*Sx*128];     // [group][c] raw max of layer3 pre-BN
__device__ uint32_t g_W1h[64*40];
__device__ uint32_t g_W1l[64*40];
__device__ uint32_t g_W2h[64*32];
__device__ uint32_t g_W2l[64*32];
__device__ uint32_t g_W3h[128*32];
__device__ uint32_t g_W3l[128*32];
__device__ float g_sum[384];
__device__ float g_sq[384];
__device__ float g_a[384];
__device__ float g_bb[384];

// ---------------- helpers ----------------
__device__ __forceinline__ uint32_t packh2(float a, float b) {
    __half2 h = __halves2half2(__float2half_rn(a), __float2half_rn(b));
    return *reinterpret_cast<uint32_t*>(&h);
}
__device__ __forceinline__ void split2(float a, float b, uint32_t &hi, uint32_t &lo) {
    __half h0 = __float2half_rn(a), h1 = __float2half_rn(b);
    __half2 hh = __halves2half2(h0, h1);
    hi = *reinterpret_cast<uint32_t*>(&hh);
    lo = packh2(a - __half2float(h0), b - __half2float(h1));
}
__device__ __forceinline__ void mma16816(float* d, const uint32_t* a, const uint32_t* b) {
    asm volatile(
        "mma.sync.aligned.m16n8k16.row.col.f32.f16.f16.f32 "
        "{%0,%1,%2,%3}, {%4,%5,%6,%7}, {%8,%9}, {%0,%1,%2,%3};"
        : "+f"(d[0]), "+f"(d[1]), "+f"(d[2]), "+f"(d[3])
        : "r"(a[0]), "r"(a[1]), "r"(a[2]), "r"(a[3]), "r"(b[0]), "r"(b[1]));
}
__device__ __forceinline__ ull packf2(float lo, float hi) {
    ull r; asm("mov.b64 %0, {%1, %2};" : "=l"(r) : "f"(lo), "f"(hi)); return r;
}
__device__ __forceinline__ float2 unpackf2(ull v) {
    float lo, hi; asm("mov.b64 {%0, %1}, %2;" : "=f"(lo), "=f"(hi) : "l"(v));
    return make_float2(lo, hi);
}
__device__ __forceinline__ ull add2(ull a, ull b) {
    ull r; asm("add.rn.f32x2 %0, %1, %2;" : "=l"(r) : "l"(a), "l"(b)); return r;
}
__device__ __forceinline__ ull mul2(ull a, ull b) {
    ull r; asm("mul.rn.f32x2 %0, %1, %2;" : "=l"(r) : "l"(a), "l"(b)); return r;
}
__device__ __forceinline__ ull fma2v(ull a, ull b, ull c) {
    ull r; asm("fma.rn.f32x2 %0, %1, %2, %3;" : "=l"(r) : "l"(a), "l"(b), "l"(c)); return r;
}

// =================================================================
// MEGA KERNEL: role by blockIdx
//   [0,16)        fps (wave-1 resident by bid -> guaranteed progress)
//   [16,4112)     transpose pts -> ptsT
//   4112          weight split prep + stats zero
//   [4113,6161)   ball query (spin-waits on fps progress)
// =================================================================
__global__ __launch_bounds__(256) void mega_kernel(const float* __restrict__ xyz,
                                                   const float* __restrict__ pts,
                                                   const float* __restrict__ W0,
                                                   const float* __restrict__ W1,
                                                   const float* __restrict__ W2,
                                                   float* __restrict__ out) {
    int bid = blockIdx.x;
    int t = threadIdx.x;

    if (bid < 16) {
        // ---------------- FPS role ----------------
        int b = bid;
        int lane = t & 31, w = t >> 5;
        const float* xb = xyz + (size_t)b*3*Nx;
        ull px2[8], py2[8], pz2[8], dst2[8];
#pragma unroll
        for (int j = 0; j < 8; j++) {
            int n = (2*j)*256 + t;
            px2[j] = packf2(xb[n],      xb[n + 256]);
            py2[j] = packf2(xb[Nx+n],   xb[Nx+n + 256]);
            pz2[j] = packf2(xb[2*Nx+n], xb[2*Nx+n + 256]);
            dst2[j] = packf2(1e10f, 1e10f);
        }
        __shared__ ull s_red[2][8];
        int far = 0;
        for (int s = 0; s < Sx; s++) {
            float cx = __ldg(xb + far), cy = __ldg(xb + Nx + far), cz = __ldg(xb + 2*Nx + far);
            if (t == 0) {
                out[b*3*Sx + s] = cx; out[b*3*Sx + Sx + s] = cy; out[b*3*Sx + 2*Sx + s] = cz;
                g_centers[(b*Sx+s)*3+0] = cx; g_centers[(b*Sx+s)*3+1] = cy; g_centers[(b*Sx+s)*3+2] = cz;
                if ((s & 3) == 3) {
                    __threadfence();
                    *(volatile int*)&g_prog[b] = s + 1;
                }
            }
            ull ncx = packf2(-cx, -cx), ncy = packf2(-cy, -cy), ncz = packf2(-cz, -cz);
            float best = -1.f; int bn = 0;
#pragma unroll
            for (int j = 0; j < 8; j++) {
                ull dx = add2(px2[j], ncx);
                ull dy = add2(py2[j], ncy);
                ull dz = add2(pz2[j], ncz);
                ull d  = mul2(dx, dx);
                d = fma2v(dy, dy, d);
                d = fma2v(dz, dz, d);
                float2 df = unpackf2(d);
                float2 ds = unpackf2(dst2[j]);
                float nd0 = fminf(ds.x, df.x);
                float nd1 = fminf(ds.y, df.y);
                dst2[j] = packf2(nd0, nd1);
                int n0 = (2*j)*256 + t;
                if (nd0 > best) { best = nd0; bn = n0; }
                if (nd1 > best) { best = nd1; bn = n0 + 256; }
            }
            unsigned ub = __float_as_uint(best);
            unsigned wmax = __reduce_max_sync(0xffffffffu, ub);
            unsigned cand = (ub == wmax) ? (unsigned)bn : 0xffffffffu;
            unsigned bmin = __reduce_min_sync(0xffffffffu, cand);
            if (lane == 0)
                s_red[s & 1][w] = ((ull)wmax << 32) | (unsigned)(0x7FFFFFFF - (int)bmin);
            __syncthreads();
            ull k = 0;
#pragma unroll
            for (int j = 0; j < 8; j++) { ull v = s_red[s & 1][j]; if (v > k) k = v; }
            far = 0x7FFFFFFF - (int)(unsigned)(k & 0xFFFFFFFFull);
        }
    } else if (bid < 4112) {
        // ---------------- transpose role ----------------
        __shared__ float tile[32][33];
        int tb = bid - 16;
        int b = tb >> 8;
        int tl = tb & 255;
        int n0 = (tl >> 1) * 32;
        int d0 = (tl & 1) * 32;
        int tx = t & 31, ty0 = t >> 5;
        for (int k = ty0; k < 32; k += 8)
            tile[k][tx] = pts[((size_t)b*Dx + d0 + k)*Nx + n0 + tx];
        __syncthreads();
        for (int k = ty0; k < 32; k += 8)
            g_ptsT[((size_t)b*Nx + n0 + k)*Dx + d0 + tx] = tile[tx][k];
    } else if (bid == 4112) {
        // ---------------- wprep + stats-zero role ----------------
        for (int i = t; i < 384; i += 256) { g_sum[i] = 0.f; g_sq[i] = 0.f; }
        for (int i = t; i < 64*40; i += 256) {
            int o = i / 40, c2 = i % 40;
            float wv[2];
#pragma unroll
            for (int j = 0; j < 2; j++) {
                int ch = 2*c2 + j;
                if (ch < 64)      wv[j] = W0[o*67 + 3 + ch];
                else if (ch < 67) wv[j] = W0[o*67 + (ch - 64)];
                else              wv[j] = 0.f;
            }
            split2(wv[0], wv[1], g_W1h[i], g_W1l[i]);
        }
        for (int i = t; i < 64*32; i += 256) {
            int o = i >> 5, c2 = i & 31;
            split2(W1[o*64 + 2*c2], W1[o*64 + 2*c2 + 1], g_W2h[i], g_W2l[i]);
        }
        for (int i = t; i < 128*32; i += 256) {
            int o = i >> 5, c2 = i & 31;
            split2(W2[o*64 + 2*c2], W2[o*64 + 2*c2 + 1], g_W3h[i], g_W3l[i]);
        }
    } else {
        // ---------------- ball-query role (spin on fps progress) ----------------
        int blk = bid - 4113;
        int b = blk >> 7;
        int w = t >> 5;
        int s = (blk & 127)*8 + w;
        int lane = t & 31;
        __shared__ int buf[8][32];

        // wait until center s is published by fps block b
        {
            int need = s + 1;
            volatile int* vp = &g_prog[b];
            int pr = *vp;
            while (pr < need) {
                unsigned slp = (unsigned)(need - pr) * 400u;
                if (slp > 8192u) slp = 8192u;
                __nanosleep(slp);
                pr = *vp;
            }
            __threadfence();   // acquire: order center loads after flag read
        }

        const float* xb = xyz + (size_t)b*3*Nx;
        float cx = g_centers[(b*Sx+s)*3+0], cy = g_centers[(b*Sx+s)*3+1], cz = g_centers[(b*Sx+s)*3+2];
        float s2 = (cx*cx + cy*cy) + cz*cz;
        int cnt = 0;
        for (int base = 0; base < Nx; base += 128) {
            int n0 = base + lane*4;
            float4 X4 = *reinterpret_cast<const float4*>(xb + n0);
            float4 Y4 = *reinterpret_cast<const float4*>(xb + Nx + n0);
            float4 Z4 = *reinterpret_cast<const float4*>(xb + 2*Nx + n0);
            unsigned msk = 0;
            { float dot = (cx*X4.x + cy*Y4.x) + cz*Z4.x; float d2 = (X4.x*X4.x + Y4.x*Y4.x) + Z4.x*Z4.x;
              float d = -2.f*dot; d += s2; d += d2; if (!(d > 0.01f)) msk |= 1u; }
            { float dot = (cx*X4.y + cy*Y4.y) + cz*Z4.y; float d2 = (X4.y*X4.y + Y4.y*Y4.y) + Z4.y*Z4.y;
              float d = -2.f*dot; d += s2; d += d2; if (!(d > 0.01f)) msk |= 2u; }
            { float dot = (cx*X4.z + cy*Y4.z) + cz*Z4.z; float d2 = (X4.z*X4.z + Y4.z*Y4.z) + Z4.z*Z4.z;
              float d = -2.f*dot; d += s2; d += d2; if (!(d > 0.01f)) msk |= 4u; }
            { float dot = (cx*X4.w + cy*Y4.w) + cz*Z4.w; float d2 = (X4.w*X4.w + Y4.w*Y4.w) + Z4.w*Z4.w;
              float d = -2.f*dot; d += s2; d += d2; if (!(d > 0.01f)) msk |= 8u; }
            unsigned anyhit = __ballot_sync(0xffffffffu, msk != 0);
            if (anyhit == 0u) continue;
            int tc = __popc(msk);
            int inc = tc;
#pragma unroll
            for (int d = 1; d < 32; d <<= 1) {
                int v = __shfl_up_sync(0xffffffffu, inc, d);
                if (lane >= d) inc += v;
            }
            int excl = inc - tc;
            int total = __shfl_sync(0xffffffffu, inc, 31);
            int pos = cnt + excl;
#pragma unroll
            for (int j = 0; j < 4; j++) {
                if (msk & (1u << j)) { if (pos < Kx) buf[w][pos] = n0 + j; pos++; }
            }
            cnt += total;
            if (cnt >= Kx) break;
        }
        __syncwarp();
        int nv = cnt < Kx ? cnt : Kx;
        int first = buf[w][0];
        int v = (lane < nv) ? buf[w][lane] : first;
        g_gidx[(b*Sx + s)*Kx + lane] = v;
    }
}

// ================= layer 1: gather + mma.sync fp16-split (K=80) =================
__global__ __launch_bounds__(256) void mlp1_mma_kernel(const float* __restrict__ xyz,
                                                       const float* __restrict__ bias,
                                                       float* __restrict__ Y,
                                                       float* __restrict__ gsum,
                                                       float* __restrict__ gsq) {
    constexpr int PITCH = 44;
    constexpr int NOUT = 64;
    constexpr int MW = 2, NFR = 4;
    extern __shared__ uint32_t sm[];
    uint32_t* s_xh = sm;
    uint32_t* s_xl = sm + 128*PITCH;
    uint32_t* s_wh = sm + 256*PITCH;
    uint32_t* s_wl = s_wh + NOUT*PITCH;
    float* s_bias = reinterpret_cast<float*>(s_wl + NOUT*PITCH);
    float* s_sum = s_bias + NOUT;
    float* s_sq  = s_sum + NOUT;

    int tid = threadIdx.x;
    int wid = tid >> 5, lane = tid & 31;
    int qr = lane >> 2, qc = lane & 3;
    size_t p0 = (size_t)blockIdx.x * 128;

    if (tid < NOUT) { s_bias[tid] = bias[tid]; s_sum[tid] = 0.f; s_sq[tid] = 0.f; }
    for (int i = tid; i < NOUT*40; i += 256) {
        int o = i / 40, c2 = i % 40;
        s_wh[o*PITCH + c2] = g_W1h[i];
        s_wl[o*PITCH + c2] = g_W1l[i];
    }
    {
        int p = tid >> 1, h = tid & 1;
        size_t pp = p0 + p;
        int bs = (int)(pp >> 5);
        int b = bs >> 10;
        int idx = g_gidx[pp];
        const float4* row = reinterpret_cast<const float4*>(g_ptsT + ((size_t)b*Nx + idx)*Dx) + h*8;
#pragma unroll
        for (int j = 0; j < 8; j++) {
            float4 v = row[j];
            int c2 = h*16 + 2*j;
            split2(v.x, v.y, s_xh[p*PITCH + c2],     s_xl[p*PITCH + c2]);
            split2(v.z, v.w, s_xh[p*PITCH + c2 + 1], s_xl[p*PITCH + c2 + 1]);
        }
        if (h == 1) {
            float cx = g_centers[bs*3+0], cy = g_centers[bs*3+1], cz = g_centers[bs*3+2];
            const float* xb = xyz + (size_t)b*3*Nx;
            float dx = __ldg(xb + idx)        - cx;
            float dy = __ldg(xb + Nx + idx)   - cy;
            float dz = __ldg(xb + 2*Nx + idx) - cz;
            split2(dx, dy, s_xh[p*PITCH + 32], s_xl[p*PITCH + 32]);
            split2(dz, 0.f, s_xh[p*PITCH + 33], s_xl[p*PITCH + 33]);
#pragma unroll
            for (int c2 = 34; c2 < 40; c2++) { s_xh[p*PITCH + c2] = 0u; s_xl[p*PITCH + c2] = 0u; }
        }
    }
    __syncthreads();

    int mw = wid % MW, nw = wid / MW;
    int mbase = mw * 32;
    int pbase = nw * 32;

    float d[2][NFR][4];
#pragma unroll
    for (int mf = 0; mf < 2; mf++)
#pragma unroll
        for (int nf = 0; nf < NFR; nf++)
#pragma unroll
            for (int j = 0; j < 4; j++) d[mf][nf][j] = 0.f;

#pragma unroll
    for (int pass = 0; pass < 3; pass++) {
        const uint32_t* wsrc = (pass == 2) ? s_wl : s_wh;
        const uint32_t* xsrc = (pass == 1) ? s_xl : s_xh;
#pragma unroll
        for (int ks = 0; ks < 5; ks++) {
            int k0 = ks*8;
            uint32_t a[2][4];
#pragma unroll
            for (int mf = 0; mf < 2; mf++) {
                int r0 = mbase + mf*16 + qr;
                a[mf][0] = wsrc[r0*PITCH + k0 + qc];
                a[mf][1] = wsrc[(r0+8)*PITCH + k0 + qc];
                a[mf][2] = wsrc[r0*PITCH + k0 + qc + 4];
                a[mf][3] = wsrc[(r0+8)*PITCH + k0 + qc + 4];
            }
            uint32_t bb[NFR][2];
#pragma unroll
            for (int nf = 0; nf < NFR; nf++) {
                int p = pbase + nf*8 + qr;
                bb[nf][0] = xsrc[p*PITCH + k0 + qc];
                bb[nf][1] = xsrc[p*PITCH + k0 + qc + 4];
            }
#pragma unroll
            for (int mf = 0; mf < 2; mf++)
#pragma unroll
                for (int nf = 0; nf < NFR; nf++)
                    mma16816(d[mf][nf], a[mf], bb[nf]);
        }
    }

#pragma unroll
    for (int mf = 0; mf < 2; mf++) {
        int r0 = mbase + mf*16 + qr;
        float b0 = s_bias[r0], b8 = s_bias[r0 + 8];
        float s0 = 0.f, q0 = 0.f, s8 = 0.f, q8 = 0.f;
#pragma unroll
        for (int nf = 0; nf < NFR; nf++) {
            int p = pbase + nf*8 + 2*qc;
            float y0 = d[mf][nf][0] + b0, y1 = d[mf][nf][1] + b0;
            float y2 = d[mf][nf][2] + b8, y3 = d[mf][nf][3] + b8;
            *reinterpret_cast<float2*>(Y + (size_t)r0*Px + p0 + p)     = make_float2(y0, y1);
            *reinterpret_cast<float2*>(Y + (size_t)(r0+8)*Px + p0 + p) = make_float2(y2, y3);
            s0 += y0 + y1; q0 += y0*y0 + y1*y1;
            s8 += y2 + y3; q8 += y2*y2 + y3*y3;
        }
        s0 += __shfl_xor_sync(0xffffffffu, s0, 1); s0 += __shfl_xor_sync(0xffffffffu, s0, 2);
        q0 += __shfl_xor_sync(0xffffffffu, q0, 1); q0 += __shfl_xor_sync(0xffffffffu, q0, 2);
        s8 += __shfl_xor_sync(0xffffffffu, s8, 1); s8 += __shfl_xor_sync(0xffffffffu, s8, 2);
        q8 += __shfl_xor_sync(0xffffffffu, q8, 1); q8 += __shfl_xor_sync(0xffffffffu, q8, 2);
        if (qc == 0) {
            atomicAdd(&s_sum[r0], s0);     atomicAdd(&s_sq[r0], q0);
            atomicAdd(&s_sum[r0 + 8], s8); atomicAdd(&s_sq[r0 + 8], q8);
        }
    }
    __syncthreads();
    if (tid < NOUT) {
        atomicAdd(gsum + tid, s_sum[tid]);
        atomicAdd(gsq  + tid, s_sq[tid]);
    }
}

// ================= layer 2 =================
__global__ __launch_bounds__(256) void mlp2_mma_kernel(const float* __restrict__ X,
                                                       const uint32_t* __restrict__ Wh,
                                                       const uint32_t* __restrict__ Wl,
                                                       const float* __restrict__ bias,
                                                       const float* __restrict__ Aarr,
                                                       const float* __restrict__ Barr,
                                                       float* __restrict__ Y,
                                                       float* __restrict__ gsum,
                                                       float* __restrict__ gsq) {
    constexpr int PITCH = 36;
    constexpr int NOUT = 64;
    constexpr int MW = 2, NFR = 4;
    extern __shared__ uint32_t sm[];
    uint32_t* s_xh = sm;
    uint32_t* s_xl = sm + 128*PITCH;
    uint32_t* s_wh = sm + 256*PITCH;
    uint32_t* s_wl = s_wh + NOUT*PITCH;
    float* s_bias = reinterpret_cast<float*>(s_wl + NOUT*PITCH);
    float* s_sum = s_bias + NOUT;
    float* s_sq  = s_sum + NOUT;

    int tid = threadIdx.x;
    int wid = tid >> 5, lane = tid & 31;
    int qr = lane >> 2, qc = lane & 3;
    size_t p0 = (size_t)blockIdx.x * 128;

    if (tid < NOUT) { s_bias[tid] = bias[tid]; s_sum[tid] = 0.f; s_sq[tid] = 0.f; }
    for (int i = tid; i < NOUT*32; i += 256) {
        int o = i >> 5, c2 = i & 31;
        s_wh[o*PITCH + c2] = Wh[i];
        s_wl[o*PITCH + c2] = Wl[i];
    }
    {
        int p = tid & 127;
        int ch0 = (tid >> 7) * 32;
#pragma unroll
        for (int j = 0; j < 16; j++) {
            int c = ch0 + 2*j;
            float v0 = X[(size_t)c*Px + p0 + p];
            float v1 = X[(size_t)(c+1)*Px + p0 + p];
            v0 = fmaxf(fmaf(v0, Aarr[c],   Barr[c]),   0.f);
            v1 = fmaxf(fmaf(v1, Aarr[c+1], Barr[c+1]), 0.f);
            split2(v0, v1, s_xh[p*PITCH + (c >> 1)], s_xl[p*PITCH + (c >> 1)]);
        }
    }
    __syncthreads();

    int mw = wid % MW, nw = wid / MW;
    int mbase = mw * 32;
    int pbase = nw * 32;

    float d[2][NFR][4];
#pragma unroll
    for (int mf = 0; mf < 2; mf++)
#pragma unroll
        for (int nf = 0; nf < NFR; nf++)
#pragma unroll
            for (int j = 0; j < 4; j++) d[mf][nf][j] = 0.f;

#pragma unroll
    for (int pass = 0; pass < 3; pass++) {
        const uint32_t* wsrc = (pass == 2) ? s_wl : s_wh;
        const uint32_t* xsrc = (pass == 1) ? s_xl : s_xh;
#pragma unroll
        for (int k0 = 0; k0 < 32; k0 += 8) {
            uint32_t a[2][4];
#pragma unroll
            for (int mf = 0; mf < 2; mf++) {
                int r0 = mbase + mf*16 + qr;
                a[mf][0] = wsrc[r0*PITCH + k0 + qc];
                a[mf][1] = wsrc[(r0+8)*PITCH + k0 + qc];
                a[mf][2] = wsrc[r0*PITCH + k0 + qc + 4];
                a[mf][3] = wsrc[(r0+8)*PITCH + k0 + qc + 4];
            }
            uint32_t bb[NFR][2];
#pragma unroll
            for (int nf = 0; nf < NFR; nf++) {
                int p = pbase + nf*8 + qr;
                bb[nf][0] = xsrc[p*PITCH + k0 + qc];
                bb[nf][1] = xsrc[p*PITCH + k0 + qc + 4];
            }
#pragma unroll
            for (int mf = 0; mf < 2; mf++)
#pragma unroll
                for (int nf = 0; nf < NFR; nf++)
                    mma16816(d[mf][nf], a[mf], bb[nf]);
        }
    }

#pragma unroll
    for (int mf = 0; mf < 2; mf++) {
        int r0 = mbase + mf*16 + qr;
        float b0 = s_bias[r0], b8 = s_bias[r0 + 8];
        float s0 = 0.f, q0 = 0.f, s8 = 0.f, q8 = 0.f;
#pragma unroll
        for (int nf = 0; nf < NFR; nf++) {
            int p = pbase + nf*8 + 2*qc;
            float y0 = d[mf][nf][0] + b0, y1 = d[mf][nf][1] + b0;
            float y2 = d[mf][nf][2] + b8, y3 = d[mf][nf][3] + b8;
            *reinterpret_cast<float2*>(Y + (size_t)r0*Px + p0 + p)     = make_float2(y0, y1);
            *reinterpret_cast<float2*>(Y + (size_t)(r0+8)*Px + p0 + p) = make_float2(y2, y3);
            s0 += y0 + y1; q0 += y0*y0 + y1*y1;
            s8 += y2 + y3; q8 += y2*y2 + y3*y3;
        }
        s0 += __shfl_xor_sync(0xffffffffu, s0, 1); s0 += __shfl_xor_sync(0xffffffffu, s0, 2);
        q0 += __shfl_xor_sync(0xffffffffu, q0, 1); q0 += __shfl_xor_sync(0xffffffffu, q0, 2);
        s8 += __shfl_xor_sync(0xffffffffu, s8, 1); s8 += __shfl_xor_sync(0xffffffffu, s8, 2);
        q8 += __shfl_xor_sync(0xffffffffu, q8, 1); q8 += __shfl_xor_sync(0xffffffffu, q8, 2);
        if (qc == 0) {
            atomicAdd(&s_sum[r0], s0);     atomicAdd(&s_sq[r0], q0);
            atomicAdd(&s_sum[r0 + 8], s8); atomicAdd(&s_sq[r0 + 8], q8);
        }
    }
    __syncthreads();
    if (tid < NOUT) {
        atomicAdd(gsum + tid, s_sum[tid]);
        atomicAdd(gsq  + tid, s_sq[tid]);
    }
}

// ================= layer 3: stats + in-register group-max (no Y store) =========
__global__ __launch_bounds__(256) void mlp3_mma_kernel(const float* __restrict__ X,
                                                       const uint32_t* __restrict__ Wh,
                                                       const uint32_t* __restrict__ Wl,
                                                       const float* __restrict__ bias,
                                                       const float* __restrict__ Aarr,
                                                       const float* __restrict__ Barr,
                                                       float* __restrict__ gmax,
                                                       float* __restrict__ gsum,
                                                       float* __restrict__ gsq) {
    constexpr int PITCH = 36;
    constexpr int NOUT = 128;
    constexpr int MW = 4, NFR = 8;
    extern __shared__ uint32_t sm[];
    uint32_t* s_xh = sm;
    uint32_t* s_xl = sm + 128*PITCH;
    uint32_t* s_wh = sm + 256*PITCH;
    uint32_t* s_wl = s_wh + NOUT*PITCH;
    float* s_bias = reinterpret_cast<float*>(s_wl + NOUT*PITCH);
    float* s_sum = s_bias + NOUT;
    float* s_sq  = s_sum + NOUT;

    int tid = threadIdx.x;
    int wid = tid >> 5, lane = tid & 31;
    int qr = lane >> 2, qc = lane & 3;
    size_t p0 = (size_t)blockIdx.x * 128;

    if (tid < NOUT) { s_bias[tid] = bias[tid]; s_sum[tid] = 0.f; s_sq[tid] = 0.f; }
    for (int i = tid; i < NOUT*32; i += 256) {
        int o = i >> 5, c2 = i & 31;
        s_wh[o*PITCH + c2] = Wh[i];
        s_wl[o*PITCH + c2] = Wl[i];
    }
    {
        int p = tid & 127;
        int ch0 = (tid >> 7) * 32;
#pragma unroll
        for (int j = 0; j < 16; j++) {
            int c = ch0 + 2*j;
            float v0 = X[(size_t)c*Px + p0 + p];
            float v1 = X[(size_t)(c+1)*Px + p0 + p];
            v0 = fmaxf(fmaf(v0, Aarr[c],   Barr[c]),   0.f);
            v1 = fmaxf(fmaf(v1, Aarr[c+1], Barr[c+1]), 0.f);
            split2(v0, v1, s_xh[p*PITCH + (c >> 1)], s_xl[p*PITCH + (c >> 1)]);
        }
    }
    __syncthreads();

    int mw = wid % MW, nw = wid / MW;
    int mbase = mw * 32;
    int pbase = nw * 64;

    float d[2][NFR][4];
#pragma unroll
    for (int mf = 0; mf < 2; mf++)
#pragma unroll
        for (int nf = 0; nf < NFR; nf++)
#pragma unroll
            for (int j = 0; j < 4; j++) d[mf][nf][j] = 0.f;

#pragma unroll
    for (int pass = 0; pass < 3; pass++) {
        const uint32_t* wsrc = (pass == 2) ? s_wl : s_wh;
        const uint32_t* xsrc = (pass == 1) ? s_xl : s_xh;
#pragma unroll
        for (int k0 = 0; k0 < 32; k0 += 8) {
            uint32_t a[2][4];
#pragma unroll
            for (int mf = 0; mf < 2; mf++) {
                int r0 = mbase + mf*16 + qr;
                a[mf][0] = wsrc[r0*PITCH + k0 + qc];
                a[mf][1] = wsrc[(r0+8)*PITCH + k0 + qc];
                a[mf][2] = wsrc[r0*PITCH + k0 + qc + 4];
                a[mf][3] = wsrc[(r0+8)*PITCH + k0 + qc + 4];
            }
            uint32_t bb[NFR][2];
#pragma unroll
            for (int nf = 0; nf < NFR; nf++) {
                int p = pbase + nf*8 + qr;
                bb[nf][0] = xsrc[p*PITCH + k0 + qc];
                bb[nf][1] = xsrc[p*PITCH + k0 + qc + 4];
            }
#pragma unroll
            for (int mf = 0; mf < 2; mf++)
#pragma unroll
                for (int nf = 0; nf < NFR; nf++)
                    mma16816(d[mf][nf], a[mf], bb[nf]);
        }
    }

#pragma unroll
    for (int mf = 0; mf < 2; mf++) {
        int r0 = mbase + mf*16 + qr;
        float b0 = s_bias[r0], b8 = s_bias[r0 + 8];
        float s0 = 0.f, q0 = 0.f, s8 = 0.f, q8 = 0.f;
        float m0[2] = {-3.4e38f, -3.4e38f};
        float m8[2] = {-3.4e38f, -3.4e38f};
#pragma unroll
        for (int nf = 0; nf < NFR; nf++) {
            int g = nf >> 2;
            float y0 = d[mf][nf][0] + b0, y1 = d[mf][nf][1] + b0;
            float y2 = d[mf][nf][2] + b8, y3 = d[mf][nf][3] + b8;
            s0 += y0 + y1; q0 += y0*y0 + y1*y1;
            s8 += y2 + y3; q8 += y2*y2 + y3*y3;
            m0[g] = fmaxf(m0[g], fmaxf(y0, y1));
            m8[g] = fmaxf(m8[g], fmaxf(y2, y3));
        }
        s0 += __shfl_xor_sync(0xffffffffu, s0, 1); s0 += __shfl_xor_sync(0xffffffffu, s0, 2);
        q0 += __shfl_xor_sync(0xffffffffu, q0, 1); q0 += __shfl_xor_sync(0xffffffffu, q0, 2);
        s8 += __shfl_xor_sync(0xffffffffu, s8, 1); s8 += __shfl_xor_sync(0xffffffffu, s8, 2);
        q8 += __shfl_xor_sync(0xffffffffu, q8, 1); q8 += __shfl_xor_sync(0xffffffffu, q8, 2);
#pragma unroll
        for (int g = 0; g < 2; g++) {
            m0[g] = fmaxf(m0[g], __shfl_xor_sync(0xffffffffu, m0[g], 1));
            m0[g] = fmaxf(m0[g], __shfl_xor_sync(0xffffffffu, m0[g], 2));
            m8[g] = fmaxf(m8[g], __shfl_xor_sync(0xffffffffu, m8[g], 1));
            m8[g] = fmaxf(m8[g], __shfl_xor_sync(0xffffffffu, m8[g], 2));
        }
        if (qc == 0) {
            atomicAdd(&s_sum[r0], s0);     atomicAdd(&s_sq[r0], q0);
            atomicAdd(&s_sum[r0 + 8], s8); atomicAdd(&s_sq[r0 + 8], q8);
            int gbase = blockIdx.x*4 + nw*2;
#pragma unroll
            for (int g = 0; g < 2; g++) {
                gmax[(size_t)(gbase + g)*128 + r0]     = m0[g];
                gmax[(size_t)(gbase + g)*128 + r0 + 8] = m8[g];
            }
        }
    }
    __syncthreads();
    if (tid < NOUT) {
        atomicAdd(gsum + tid, s_sum[tid]);
        atomicAdd(gsq  + tid, s_sq[tid]);
    }
}

// ---------------- BN finalize ----------------
__global__ void finalize_kernel(int layer, const float* __restrict__ gamma,
                                const float* __restrict__ beta, int C) {
    int c = threadIdx.x;
    if (c >= C) return;
    float S = g_sum[layer*128 + c], Q = g_sq[layer*128 + c];
    float m = S * (1.f/524288.f);
    float var = Q * (1.f/524288.f) - m*m;
    float A = gamma[c] * rsqrtf(var + 1e-5f);
    g_a[layer*128 + c]  = A;
    g_bb[layer*128 + c] = beta[c] - m*A;
}

// ---------------- final: BN+ReLU of group-max, transposed store ----------------
__global__ void gfin_kernel(const float* __restrict__ gmax,
                            const float* __restrict__ A,
                            const float* __restrict__ B,
                            float* __restrict__ out) {
    __shared__ float t[32][33];
    int s0 = blockIdx.x*32, c0 = blockIdx.y*32, b = blockIdx.z;
    int tx = threadIdx.x, ty = threadIdx.y;
    for (int k = ty; k < 32; k += 8)
        t[k][tx] = gmax[(size_t)(b*1024 + s0 + k)*128 + c0 + tx];
    __syncthreads();
    for (int k = ty; k < 32; k += 8) {
        int c = c0 + k;
        float v = fmaxf(fmaf(t[tx][k], A[c], B[c]), 0.f);
        out[16*3*1024 + ((size_t)(b*128 + c))*1024 + s0 + tx] = v;
    }
}

// ---------------- launch ----------------
extern "C" void kernel_launch(void* const* d_in, const int* in_sizes, int n_in,
                              void* d_out, int out_size) {
    const float* xyz = (const float*)d_in[0];
    const float* pts = (const float*)d_in[1];
    const float* W0 = (const float*)d_in[2];
    const float* b0 = (const float*)d_in[3];
    const float* ga0 = (const float*)d_in[4];
    const float* be0 = (const float*)d_in[5];
    const float* W1 = (const float*)d_in[6];
    const float* b1 = (const float*)d_in[7];
    const float* ga1 = (const float*)d_in[8];
    const float* be1 = (const float*)d_in[9];
    const float* W2 = (const float*)d_in[10];
    const float* b2 = (const float*)d_in[11];
    const float* ga2 = (const float*)d_in[12];
    const float* be2 = (const float*)d_in[13];
    float* out = (float*)d_out;

    float *pY1, *pY2, *pGM, *pA, *pB, *pS, *pQ;
    uint32_t *pW2h, *pW2l, *pW3h, *pW3l;
    cudaGetSymbolAddress((void**)&pY1, g_Y1);
    cudaGetSymbolAddress((void**)&pY2, g_Y2);
    cudaGetSymbolAddress((void**)&pGM, g_gmax);
    cudaGetSymbolAddress((void**)&pA, g_a);
    cudaGetSymbolAddress((void**)&pB, g_bb);
    cudaGetSymbolAddress((void**)&pS, g_sum);
    cudaGetSymbolAddress((void**)&pQ, g_sq);
    cudaGetSymbolAddress((void**)&pW2h, g_W2h);
    cudaGetSymbolAddress((void**)&pW2l, g_W2l);
    cudaGetSymbolAddress((void**)&pW3h, g_W3h);
    cudaGetSymbolAddress((void**)&pW3l, g_W3l);

    const int smem1 = (2*128*44 + 2*64*44)*4 + 64*3*4;
    const int smem2 = (256*36 + 2*64*36)*4  + 64*3*4;
    const int smem3 = (256*36 + 2*128*36)*4 + 128*3*4;
    cudaFuncSetAttribute(mlp1_mma_kernel, cudaFuncAttributeMaxDynamicSharedMemorySize, smem1);
    cudaFuncSetAttribute(mlp2_mma_kernel, cudaFuncAttributeMaxDynamicSharedMemorySize, smem2);
    cudaFuncSetAttribute(mlp3_mma_kernel, cudaFuncAttributeMaxDynamicSharedMemorySize, smem3);

    // phase 1: fps + transpose + wprep(+stats zero) + qb, all in one kernel
    mega_kernel<<<6161, 256>>>(xyz, pts, W0, W1, W2, out);            // 1

    mlp1_mma_kernel<<<Px/128, 256, smem1>>>(xyz, b0, pY1, pS + 0, pQ + 0);  // 2
    finalize_kernel<<<1, 128>>>(0, ga0, be0, 64);                      // 3

    mlp2_mma_kernel<<<Px/128, 256, smem2>>>(pY1, pW2h, pW2l, b1, pA + 0, pB + 0,
                                            pY2, pS + 128, pQ + 128);  // 4 (captured)
    finalize_kernel<<<1, 128>>>(1, ga1, be1, 64);

    mlp3_mma_kernel<<<Px/128, 256, smem3>>>(pY2, pW3h, pW3l, b2, pA + 128, pB + 128,
                                            pGM, pS + 256, pQ + 256);
    finalize_kernel<<<1, 128>>>(2, ga2, be2, 128);

    gfin_kernel<<<dim3(32, 4, 16), dim3(32, 8)>>>(pGM, pA + 256, pB + 256, out);
}

// round 12
// speedup vs baseline: 1.9171x; 1.9171x over previous
#include <cuda_runtime.h>
#include <cuda_fp16.h>
#include <cstdint>

#define Bx 16
#define Nx 4096
#define Sx 1024
#define Kx 32
#define Dx 64
#define Px (Bx*Sx*Kx)   // 524288

typedef unsigned long long ull;

// ---------------- device scratch ----------------
__device__ float g_centers[Bx*Sx*3];
__device__ int   g_gidx[Bx*Sx*Kx];
__device__ float g_ptsT[Bx*Nx*Dx];
__device__ float g_Y1[64u*Px];          // channel-major
__device__ float g_Y2[64u*Px];          // channel-major
__device__ float g_gmax[Bx*Sx*128];     // [group][c] raw max of layer3 pre-BN
__device__ uint32_t g_W1h[64*40];
__device__ uint32_t g_W1l[64*40];
__device__ uint32_t g_W2h[64*32];
__device__ uint32_t g_W2l[64*32];
__device__ uint32_t g_W3h[128*32];
__device__ uint32_t g_W3l[128*32];
__device__ float g_sum[384];
__device__ float g_sq[384];
__device__ float g_a[384];
__device__ float g_bb[384];

// ---------------- helpers ----------------
__device__ __forceinline__ uint32_t packh2(float a, float b) {
    __half2 h = __halves2half2(__float2half_rn(a), __float2half_rn(b));
    return *reinterpret_cast<uint32_t*>(&h);
}
__device__ __forceinline__ void split2(float a, float b, uint32_t &hi, uint32_t &lo) {
    __half h0 = __float2half_rn(a), h1 = __float2half_rn(b);
    __half2 hh = __halves2half2(h0, h1);
    hi = *reinterpret_cast<uint32_t*>(&hh);
    lo = packh2(a - __half2float(h0), b - __half2float(h1));
}
__device__ __forceinline__ void mma16816(float* d, const uint32_t* a, const uint32_t* b) {
    asm volatile(
        "mma.sync.aligned.m16n8k16.row.col.f32.f16.f16.f32 "
        "{%0,%1,%2,%3}, {%4,%5,%6,%7}, {%8,%9}, {%0,%1,%2,%3};"
        : "+f"(d[0]), "+f"(d[1]), "+f"(d[2]), "+f"(d[3])
        : "r"(a[0]), "r"(a[1]), "r"(a[2]), "r"(a[3]), "r"(b[0]), "r"(b[1]));
}
__device__ __forceinline__ uint32_t sm_u32(const void* p) {
    return (uint32_t)__cvta_generic_to_shared(p);
}
__device__ __forceinline__ void ldsm4(uint32_t* r, uint32_t addr) {
    asm volatile("ldmatrix.sync.aligned.m8n8.x4.shared.b16 {%0,%1,%2,%3}, [%4];"
        : "=r"(r[0]), "=r"(r[1]), "=r"(r[2]), "=r"(r[3]) : "r"(addr));
}

// ---------------- transpose points (B,64,N) -> ptsT (B,N,64) ----------------
__global__ void transpose_kernel(const float* __restrict__ pts) {
    __shared__ float tile[32][33];
    int b = blockIdx.z, n0 = blockIdx.x*32, d0 = blockIdx.y*32;
    int tx = threadIdx.x, ty = threadIdx.y;
    tile[ty][tx] = pts[((size_t)b*Dx + d0 + ty)*Nx + n0 + tx];
    __syncthreads();
    g_ptsT[((size_t)b*Nx + n0 + ty)*Dx + d0 + tx] = tile[tx][ty];
}

// ---------------- weight split prep (all 3 layers) ----------------
__global__ void wprep_kernel(const float* __restrict__ W0,
                             const float* __restrict__ W1,
                             const float* __restrict__ W2) {
    int i = blockIdx.x*256 + threadIdx.x;
    if (i < 64*40) {
        int o = i / 40, c2 = i % 40;
        float w[2];
#pragma unroll
        for (int j = 0; j < 2; j++) {
            int ch = 2*c2 + j;
            if (ch < 64)      w[j] = W0[o*67 + 3 + ch];
            else if (ch < 67) w[j] = W0[o*67 + (ch - 64)];
            else              w[j] = 0.f;
        }
        split2(w[0], w[1], g_W1h[i], g_W1l[i]);
    }
    if (i < 64*32) {
        int o = i >> 5, c2 = i & 31;
        split2(W1[o*64 + 2*c2], W1[o*64 + 2*c2 + 1], g_W2h[i], g_W2l[i]);
    }
    if (i < 128*32) {
        int o = i >> 5, c2 = i & 31;
        split2(W2[o*64 + 2*c2], W2[o*64 + 2*c2 + 1], g_W3h[i], g_W3l[i]);
    }
}

// ---------------- FPS: redux.sync argmax (R8 proven) ----------------
__global__ __launch_bounds__(256) void fps_kernel(const float* __restrict__ xyz,
                                                  float* __restrict__ out) {
    int b = blockIdx.x, t = threadIdx.x;
    int lane = t & 31, w = t >> 5;
    if (b == 0) {
        if (t < 256) { g_sum[t] = 0.f; g_sq[t] = 0.f; }
        if (t < 128) { g_sum[256 + t] = 0.f; g_sq[256 + t] = 0.f; }
    }
    const float* xb = xyz + (size_t)b*3*Nx;
    float px[16], py[16], pz[16], dst[16];
#pragma unroll
    for (int i = 0; i < 16; i++) {
        int n = i*256 + t;
        px[i] = xb[n]; py[i] = xb[Nx+n]; pz[i] = xb[2*Nx+n];
        dst[i] = 1e10f;
    }
    __shared__ ull s_red[2][8];
    int far = 0;
    for (int s = 0; s < Sx; s++) {
        float cx = __ldg(xb + far), cy = __ldg(xb + Nx + far), cz = __ldg(xb + 2*Nx + far);
        if (t == 0) {
            out[b*3*Sx + s] = cx; out[b*3*Sx + Sx + s] = cy; out[b*3*Sx + 2*Sx + s] = cz;
            g_centers[(b*Sx+s)*3+0] = cx; g_centers[(b*Sx+s)*3+1] = cy; g_centers[(b*Sx+s)*3+2] = cz;
        }
        float best = -1.f; int bn = 0;
#pragma unroll
        for (int i = 0; i < 16; i++) {
            float dx = px[i]-cx, dy = py[i]-cy, dz = pz[i]-cz;
            float d = (dx*dx + dy*dy) + dz*dz;
            float nd = fminf(dst[i], d);
            dst[i] = nd;
            int n = i*256 + t;
            if (nd > best) { best = nd; bn = n; }
        }
        unsigned ub = __float_as_uint(best);
        unsigned wmax = __reduce_max_sync(0xffffffffu, ub);
        unsigned cand = (ub == wmax) ? (unsigned)bn : 0xffffffffu;
        unsigned bmin = __reduce_min_sync(0xffffffffu, cand);
        if (lane == 0)
            s_red[s & 1][w] = ((ull)wmax << 32) | (unsigned)(0x7FFFFFFF - (int)bmin);
        __syncthreads();
        ull k = 0;
#pragma unroll
        for (int j = 0; j < 8; j++) { ull v = s_red[s & 1][j]; if (v > k) k = v; }
        far = 0x7FFFFFFF - (int)(unsigned)(k & 0xFFFFFFFFull);
    }
}

// ---------------- ball query (R8 proven) ----------------
__global__ __launch_bounds__(256) void qb_kernel(const float* __restrict__ xyz) {
    int blk = blockIdx.x;
    int b = blk >> 7;
    int w = threadIdx.x >> 5;
    int s = (blk & 127)*8 + w;
    int lane = threadIdx.x & 31;
    __shared__ int buf[8][32];
    const float* xb = xyz + (size_t)b*3*Nx;
    float cx = g_centers[(b*Sx+s)*3+0], cy = g_centers[(b*Sx+s)*3+1], cz = g_centers[(b*Sx+s)*3+2];
    float s2 = (cx*cx + cy*cy) + cz*cz;
    int cnt = 0;
    for (int base = 0; base < Nx; base += 128) {
        int n0 = base + lane*4;
        float4 X4 = *reinterpret_cast<const float4*>(xb + n0);
        float4 Y4 = *reinterpret_cast<const float4*>(xb + Nx + n0);
        float4 Z4 = *reinterpret_cast<const float4*>(xb + 2*Nx + n0);
        unsigned msk = 0;
        { float dot = (cx*X4.x + cy*Y4.x) + cz*Z4.x; float d2 = (X4.x*X4.x + Y4.x*Y4.x) + Z4.x*Z4.x;
          float d = -2.f*dot; d += s2; d += d2; if (!(d > 0.01f)) msk |= 1u; }
        { float dot = (cx*X4.y + cy*Y4.y) + cz*Z4.y; float d2 = (X4.y*X4.y + Y4.y*Y4.y) + Z4.y*Z4.y;
          float d = -2.f*dot; d += s2; d += d2; if (!(d > 0.01f)) msk |= 2u; }
        { float dot = (cx*X4.z + cy*Y4.z) + cz*Z4.z; float d2 = (X4.z*X4.z + Y4.z*Y4.z) + Z4.z*Z4.z;
          float d = -2.f*dot; d += s2; d += d2; if (!(d > 0.01f)) msk |= 4u; }
        { float dot = (cx*X4.w + cy*Y4.w) + cz*Z4.w; float d2 = (X4.w*X4.w + Y4.w*Y4.w) + Z4.w*Z4.w;
          float d = -2.f*dot; d += s2; d += d2; if (!(d > 0.01f)) msk |= 8u; }
        int tc = __popc(msk);
        int inc = tc;
#pragma unroll
        for (int d = 1; d < 32; d <<= 1) {
            int v = __shfl_up_sync(0xffffffffu, inc, d);
            if (lane >= d) inc += v;
        }
        int excl = inc - tc;
        int total = __shfl_sync(0xffffffffu, inc, 31);
        int pos = cnt + excl;
#pragma unroll
        for (int j = 0; j < 4; j++) {
            if (msk & (1u << j)) { if (pos < Kx) buf[w][pos] = n0 + j; pos++; }
        }
        cnt += total;
        if (cnt >= Kx) break;
    }
    __syncwarp();
    int nv = cnt < Kx ? cnt : Kx;
    int first = buf[w][0];
    int v = (lane < nv) ? buf[w][lane] : first;
    g_gidx[(b*Sx + s)*Kx + lane] = v;
}

// ================= layer 1: gather + mma.sync fp16-split (K=80), ldmatrix =====
__global__ __launch_bounds__(256) void mlp1_mma_kernel(const float* __restrict__ xyz,
                                                       const float* __restrict__ bias,
                                                       float* __restrict__ Y,
                                                       float* __restrict__ gsum,
                                                       float* __restrict__ gsq) {
    constexpr int PITCH = 44;
    constexpr int NOUT = 64;
    constexpr int MW = 2, NFR = 4;
    extern __shared__ uint32_t sm[];
    uint32_t* s_xh = sm;
    uint32_t* s_xl = sm + 128*PITCH;
    uint32_t* s_wh = sm + 256*PITCH;
    uint32_t* s_wl = s_wh + NOUT*PITCH;
    float* s_bias = reinterpret_cast<float*>(s_wl + NOUT*PITCH);
    float* s_sum = s_bias + NOUT;
    float* s_sq  = s_sum + NOUT;

    int tid = threadIdx.x;
    int wid = tid >> 5, lane = tid & 31;
    int qr = lane >> 2, qc = lane & 3;
    size_t p0 = (size_t)blockIdx.x * 128;

    if (tid < NOUT) { s_bias[tid] = bias[tid]; s_sum[tid] = 0.f; s_sq[tid] = 0.f; }
    for (int i = tid; i < NOUT*40; i += 256) {
        int o = i / 40, c2 = i % 40;
        s_wh[o*PITCH + c2] = g_W1h[i];
        s_wl[o*PITCH + c2] = g_W1l[i];
    }
    {
        int p = tid >> 1, h = tid & 1;
        size_t pp = p0 + p;
        int bs = (int)(pp >> 5);
        int b = bs >> 10;
        int idx = g_gidx[pp];
        const float4* row = reinterpret_cast<const float4*>(g_ptsT + ((size_t)b*Nx + idx)*Dx) + h*8;
#pragma unroll
        for (int j = 0; j < 8; j++) {
            float4 v = row[j];
            int c2 = h*16 + 2*j;
            split2(v.x, v.y, s_xh[p*PITCH + c2],     s_xl[p*PITCH + c2]);
            split2(v.z, v.w, s_xh[p*PITCH + c2 + 1], s_xl[p*PITCH + c2 + 1]);
        }
        if (h == 1) {
            float cx = g_centers[bs*3+0], cy = g_centers[bs*3+1], cz = g_centers[bs*3+2];
            const float* xb = xyz + (size_t)b*3*Nx;
            float dx = __ldg(xb + idx)        - cx;
            float dy = __ldg(xb + Nx + idx)   - cy;
            float dz = __ldg(xb + 2*Nx + idx) - cz;
            split2(dx, dy, s_xh[p*PITCH + 32], s_xl[p*PITCH + 32]);
            split2(dz, 0.f, s_xh[p*PITCH + 33], s_xl[p*PITCH + 33]);
#pragma unroll
            for (int c2 = 34; c2 < 40; c2++) { s_xh[p*PITCH + c2] = 0u; s_xl[p*PITCH + c2] = 0u; }
        }
    }
    __syncthreads();

    int mw = wid % MW, nw = wid / MW;
    int mbase = mw * 32;
    int pbase = nw * 32;

    // ldmatrix lane offsets (bytes)
    int tile = lane >> 3, tr = lane & 7;
    uint32_t aoff = (uint32_t)(((mbase + tr + ((tile & 1) << 3))*PITCH + ((tile >> 1) << 2)) * 4);
    uint32_t boff = (uint32_t)(((pbase + ((tile >> 1) << 3) + tr)*PITCH + ((tile & 1) << 2)) * 4);

    float d[2][NFR][4];
#pragma unroll
    for (int mf = 0; mf < 2; mf++)
#pragma unroll
        for (int nf = 0; nf < NFR; nf++)
#pragma unroll
            for (int j = 0; j < 4; j++) d[mf][nf][j] = 0.f;

#pragma unroll
    for (int pass = 0; pass < 3; pass++) {
        const uint32_t* wsrc = (pass == 2) ? s_wl : s_wh;
        const uint32_t* xsrc = (pass == 1) ? s_xl : s_xh;
        uint32_t abase = sm_u32(wsrc) + aoff;
        uint32_t bbase = sm_u32(xsrc) + boff;
#pragma unroll
        for (int ks = 0; ks < 5; ks++) {
            uint32_t a0[4], a1[4];
            ldsm4(a0, abase);
            ldsm4(a1, abase + (uint32_t)(16*PITCH*4));
            uint32_t bf[NFR][2];
#pragma unroll
            for (int np = 0; np < NFR/2; np++) {
                uint32_t r4[4];
                ldsm4(r4, bbase + (uint32_t)(np*16*PITCH*4));
                bf[2*np][0] = r4[0]; bf[2*np][1] = r4[1];
                bf[2*np+1][0] = r4[2]; bf[2*np+1][1] = r4[3];
            }
#pragma unroll
            for (int nf = 0; nf < NFR; nf++) mma16816(d[0][nf], a0, bf[nf]);
#pragma unroll
            for (int nf = 0; nf < NFR; nf++) mma16816(d[1][nf], a1, bf[nf]);
            abase += 32; bbase += 32;
        }
    }

#pragma unroll
    for (int mf = 0; mf < 2; mf++) {
        int r0 = mbase + mf*16 + qr;
        float b0 = s_bias[r0], b8 = s_bias[r0 + 8];
        float s0 = 0.f, q0 = 0.f, s8 = 0.f, q8 = 0.f;
#pragma unroll
        for (int nf = 0; nf < NFR; nf++) {
            int p = pbase + nf*8 + 2*qc;
            float y0 = d[mf][nf][0] + b0, y1 = d[mf][nf][1] + b0;
            float y2 = d[mf][nf][2] + b8, y3 = d[mf][nf][3] + b8;
            *reinterpret_cast<float2*>(Y + (size_t)r0*Px + p0 + p)     = make_float2(y0, y1);
            *reinterpret_cast<float2*>(Y + (size_t)(r0+8)*Px + p0 + p) = make_float2(y2, y3);
            s0 += y0 + y1; q0 += y0*y0 + y1*y1;
            s8 += y2 + y3; q8 += y2*y2 + y3*y3;
        }
        s0 += __shfl_xor_sync(0xffffffffu, s0, 1); s0 += __shfl_xor_sync(0xffffffffu, s0, 2);
        q0 += __shfl_xor_sync(0xffffffffu, q0, 1); q0 += __shfl_xor_sync(0xffffffffu, q0, 2);
        s8 += __shfl_xor_sync(0xffffffffu, s8, 1); s8 += __shfl_xor_sync(0xffffffffu, s8, 2);
        q8 += __shfl_xor_sync(0xffffffffu, q8, 1); q8 += __shfl_xor_sync(0xffffffffu, q8, 2);
        if (qc == 0) {
            atomicAdd(&s_sum[r0], s0);     atomicAdd(&s_sq[r0], q0);
            atomicAdd(&s_sum[r0 + 8], s8); atomicAdd(&s_sq[r0 + 8], q8);
        }
    }
    __syncthreads();
    if (tid < NOUT) {
        atomicAdd(gsum + tid, s_sum[tid]);
        atomicAdd(gsq  + tid, s_sq[tid]);
    }
}

// ================= layer 2: mma.sync fp16-split, ldmatrix =================
__global__ __launch_bounds__(256) void mlp2_mma_kernel(const float* __restrict__ X,
                                                       const uint32_t* __restrict__ Wh,
                                                       const uint32_t* __restrict__ Wl,
                                                       const float* __restrict__ bias,
                                                       const float* __restrict__ Aarr,
                                                       const float* __restrict__ Barr,
                                                       float* __restrict__ Y,
                                                       float* __restrict__ gsum,
                                                       float* __restrict__ gsq) {
    constexpr int PITCH = 36;
    constexpr int NOUT = 64;
    constexpr int MW = 2, NFR = 4;
    extern __shared__ uint32_t sm[];
    uint32_t* s_xh = sm;
    uint32_t* s_xl = sm + 128*PITCH;
    uint32_t* s_wh = sm + 256*PITCH;
    uint32_t* s_wl = s_wh + NOUT*PITCH;
    float* s_bias = reinterpret_cast<float*>(s_wl + NOUT*PITCH);
    float* s_sum = s_bias + NOUT;
    float* s_sq  = s_sum + NOUT;

    int tid = threadIdx.x;
    int wid = tid >> 5, lane = tid & 31;
    int qr = lane >> 2, qc = lane & 3;
    size_t p0 = (size_t)blockIdx.x * 128;

    if (tid < NOUT) { s_bias[tid] = bias[tid]; s_sum[tid] = 0.f; s_sq[tid] = 0.f; }
    for (int i = tid; i < NOUT*32; i += 256) {
        int o = i >> 5, c2 = i & 31;
        s_wh[o*PITCH + c2] = Wh[i];
        s_wl[o*PITCH + c2] = Wl[i];
    }
    {
        int p = tid & 127;
        int ch0 = (tid >> 7) * 32;
#pragma unroll
        for (int j = 0; j < 16; j++) {
            int c = ch0 + 2*j;
            float v0 = X[(size_t)c*Px + p0 + p];
            float v1 = X[(size_t)(c+1)*Px + p0 + p];
            v0 = fmaxf(fmaf(v0, Aarr[c],   Barr[c]),   0.f);
            v1 = fmaxf(fmaf(v1, Aarr[c+1], Barr[c+1]), 0.f);
            split2(v0, v1, s_xh[p*PITCH + (c >> 1)], s_xl[p*PITCH + (c >> 1)]);
        }
    }
    __syncthreads();

    int mw = wid % MW, nw = wid / MW;
    int mbase = mw * 32;
    int pbase = nw * 32;

    int tile = lane >> 3, tr = lane & 7;
    uint32_t aoff = (uint32_t)(((mbase + tr + ((tile & 1) << 3))*PITCH + ((tile >> 1) << 2)) * 4);
    uint32_t boff = (uint32_t)(((pbase + ((tile >> 1) << 3) + tr)*PITCH + ((tile & 1) << 2)) * 4);

    float d[2][NFR][4];
#pragma unroll
    for (int mf = 0; mf < 2; mf++)
#pragma unroll
        for (int nf = 0; nf < NFR; nf++)
#pragma unroll
            for (int j = 0; j < 4; j++) d[mf][nf][j] = 0.f;

#pragma unroll
    for (int pass = 0; pass < 3; pass++) {
        const uint32_t* wsrc = (pass == 2) ? s_wl : s_wh;
        const uint32_t* xsrc = (pass == 1) ? s_xl : s_xh;
        uint32_t abase = sm_u32(wsrc) + aoff;
        uint32_t bbase = sm_u32(xsrc) + boff;
#pragma unroll
        for (int ks = 0; ks < 4; ks++) {
            uint32_t a0[4], a1[4];
            ldsm4(a0, abase);
            ldsm4(a1, abase + (uint32_t)(16*PITCH*4));
            uint32_t bf[NFR][2];
#pragma unroll
            for (int np = 0; np < NFR/2; np++) {
                uint32_t r4[4];
                ldsm4(r4, bbase + (uint32_t)(np*16*PITCH*4));
                bf[2*np][0] = r4[0]; bf[2*np][1] = r4[1];
                bf[2*np+1][0] = r4[2]; bf[2*np+1][1] = r4[3];
            }
#pragma unroll
            for (int nf = 0; nf < NFR; nf++) mma16816(d[0][nf], a0, bf[nf]);
#pragma unroll
            for (int nf = 0; nf < NFR; nf++) mma16816(d[1][nf], a1, bf[nf]);
            abase += 32; bbase += 32;
        }
    }

#pragma unroll
    for (int mf = 0; mf < 2; mf++) {
        int r0 = mbase + mf*16 + qr;
        float b0 = s_bias[r0], b8 = s_bias[r0 + 8];
        float s0 = 0.f, q0 = 0.f, s8 = 0.f, q8 = 0.f;
#pragma unroll
        for (int nf = 0; nf < NFR; nf++) {
            int p = pbase + nf*8 + 2*qc;
            float y0 = d[mf][nf][0] + b0, y1 = d[mf][nf][1] + b0;
            float y2 = d[mf][nf][2] + b8, y3 = d[mf][nf][3] + b8;
            *reinterpret_cast<float2*>(Y + (size_t)r0*Px + p0 + p)     = make_float2(y0, y1);
            *reinterpret_cast<float2*>(Y + (size_t)(r0+8)*Px + p0 + p) = make_float2(y2, y3);
            s0 += y0 + y1; q0 += y0*y0 + y1*y1;
            s8 += y2 + y3; q8 += y2*y2 + y3*y3;
        }
        s0 += __shfl_xor_sync(0xffffffffu, s0, 1); s0 += __shfl_xor_sync(0xffffffffu, s0, 2);
        q0 += __shfl_xor_sync(0xffffffffu, q0, 1); q0 += __shfl_xor_sync(0xffffffffu, q0, 2);
        s8 += __shfl_xor_sync(0xffffffffu, s8, 1); s8 += __shfl_xor_sync(0xffffffffu, s8, 2);
        q8 += __shfl_xor_sync(0xffffffffu, q8, 1); q8 += __shfl_xor_sync(0xffffffffu, q8, 2);
        if (qc == 0) {
            atomicAdd(&s_sum[r0], s0);     atomicAdd(&s_sq[r0], q0);
            atomicAdd(&s_sum[r0 + 8], s8); atomicAdd(&s_sq[r0 + 8], q8);
        }
    }
    __syncthreads();
    if (tid < NOUT) {
        atomicAdd(gsum + tid, s_sum[tid]);
        atomicAdd(gsq  + tid, s_sq[tid]);
    }
}

// ================= layer 3: ldmatrix, stats + in-register group-max ===========
__global__ __launch_bounds__(256) void mlp3_mma_kernel(const float* __restrict__ X,
                                                       const uint32_t* __restrict__ Wh,
                                                       const uint32_t* __restrict__ Wl,
                                                       const float* __restrict__ bias,
                                                       const float* __restrict__ Aarr,
                                                       const float* __restrict__ Barr,
                                                       float* __restrict__ gmax,
                                                       float* __restrict__ gsum,
                                                       float* __restrict__ gsq) {
    constexpr int PITCH = 36;
    constexpr int NOUT = 128;
    constexpr int MW = 4, NFR = 8;
    extern __shared__ uint32_t sm[];
    uint32_t* s_xh = sm;
    uint32_t* s_xl = sm + 128*PITCH;
    uint32_t* s_wh = sm + 256*PITCH;
    uint32_t* s_wl = s_wh + NOUT*PITCH;
    float* s_bias = reinterpret_cast<float*>(s_wl + NOUT*PITCH);
    float* s_sum = s_bias + NOUT;
    float* s_sq  = s_sum + NOUT;

    int tid = threadIdx.x;
    int wid = tid >> 5, lane = tid & 31;
    int qr = lane >> 2, qc = lane & 3;
    size_t p0 = (size_t)blockIdx.x * 128;

    if (tid < NOUT) { s_bias[tid] = bias[tid]; s_sum[tid] = 0.f; s_sq[tid] = 0.f; }
    for (int i = tid; i < NOUT*32; i += 256) {
        int o = i >> 5, c2 = i & 31;
        s_wh[o*PITCH + c2] = Wh[i];
        s_wl[o*PITCH + c2] = Wl[i];
    }
    {
        int p = tid & 127;
        int ch0 = (tid >> 7) * 32;
#pragma unroll
        for (int j = 0; j < 16; j++) {
            int c = ch0 + 2*j;
            float v0 = X[(size_t)c*Px + p0 + p];
            float v1 = X[(size_t)(c+1)*Px + p0 + p];
            v0 = fmaxf(fmaf(v0, Aarr[c],   Barr[c]),   0.f);
            v1 = fmaxf(fmaf(v1, Aarr[c+1], Barr[c+1]), 0.f);
            split2(v0, v1, s_xh[p*PITCH + (c >> 1)], s_xl[p*PITCH + (c >> 1)]);
        }
    }
    __syncthreads();

    int mw = wid % MW, nw = wid / MW;
    int mbase = mw * 32;
    int pbase = nw * 64;

    int tile = lane >> 3, tr = lane & 7;
    uint32_t aoff = (uint32_t)(((mbase + tr + ((tile & 1) << 3))*PITCH + ((tile >> 1) << 2)) * 4);
    uint32_t boff = (uint32_t)(((pbase + ((tile >> 1) << 3) + tr)*PITCH + ((tile & 1) << 2)) * 4);

    float d[2][NFR][4];
#pragma unroll
    for (int mf = 0; mf < 2; mf++)
#pragma unroll
        for (int nf = 0; nf < NFR; nf++)
#pragma unroll
            for (int j = 0; j < 4; j++) d[mf][nf][j] = 0.f;

#pragma unroll
    for (int pass = 0; pass < 3; pass++) {
        const uint32_t* wsrc = (pass == 2) ? s_wl : s_wh;
        const uint32_t* xsrc = (pass == 1) ? s_xl : s_xh;
        uint32_t abase = sm_u32(wsrc) + aoff;
        uint32_t bbase = sm_u32(xsrc) + boff;
#pragma unroll
        for (int ks = 0; ks < 4; ks++) {
            uint32_t a0[4], a1[4];
            ldsm4(a0, abase);
            ldsm4(a1, abase + (uint32_t)(16*PITCH*4));
            uint32_t bf[NFR][2];
#pragma unroll
            for (int np = 0; np < NFR/2; np++) {
                uint32_t r4[4];
                ldsm4(r4, bbase + (uint32_t)(np*16*PITCH*4));
                bf[2*np][0] = r4[0]; bf[2*np][1] = r4[1];
                bf[2*np+1][0] = r4[2]; bf[2*np+1][1] = r4[3];
            }
#pragma unroll
            for (int nf = 0; nf < NFR; nf++) mma16816(d[0][nf], a0, bf[nf]);
#pragma unroll
            for (int nf = 0; nf < NFR; nf++) mma16816(d[1][nf], a1, bf[nf]);
            abase += 32; bbase += 32;
        }
    }

#pragma unroll
    for (int mf = 0; mf < 2; mf++) {
        int r0 = mbase + mf*16 + qr;
        float b0 = s_bias[r0], b8 = s_bias[r0 + 8];
        float s0 = 0.f, q0 = 0.f, s8 = 0.f, q8 = 0.f;
        float m0[2] = {-3.4e38f, -3.4e38f};
        float m8[2] = {-3.4e38f, -3.4e38f};
#pragma unroll
        for (int nf = 0; nf < NFR; nf++) {
            int g = nf >> 2;
            float y0 = d[mf][nf][0] + b0, y1 = d[mf][nf][1] + b0;
            float y2 = d[mf][nf][2] + b8, y3 = d[mf][nf][3] + b8;
            s0 += y0 + y1; q0 += y0*y0 + y1*y1;
            s8 += y2 + y3; q8 += y2*y2 + y3*y3;
            m0[g] = fmaxf(m0[g], fmaxf(y0, y1));
            m8[g] = fmaxf(m8[g], fmaxf(y2, y3));
        }
        s0 += __shfl_xor_sync(0xffffffffu, s0, 1); s0 += __shfl_xor_sync(0xffffffffu, s0, 2);
        q0 += __shfl_xor_sync(0xffffffffu, q0, 1); q0 += __shfl_xor_sync(0xffffffffu, q0, 2);
        s8 += __shfl_xor_sync(0xffffffffu, s8, 1); s8 += __shfl_xor_sync(0xffffffffu, s8, 2);
        q8 += __shfl_xor_sync(0xffffffffu, q8, 1); q8 += __shfl_xor_sync(0xffffffffu, q8, 2);
#pragma unroll
        for (int g = 0; g < 2; g++) {
            m0[g] = fmaxf(m0[g], __shfl_xor_sync(0xffffffffu, m0[g], 1));
            m0[g] = fmaxf(m0[g], __shfl_xor_sync(0xffffffffu, m0[g], 2));
            m8[g] = fmaxf(m8[g], __shfl_xor_sync(0xffffffffu, m8[g], 1));
            m8[g] = fmaxf(m8[g], __shfl_xor_sync(0xffffffffu, m8[g], 2));
        }
        if (qc == 0) {
            atomicAdd(&s_sum[r0], s0);     atomicAdd(&s_sq[r0], q0);
            atomicAdd(&s_sum[r0 + 8], s8); atomicAdd(&s_sq[r0 + 8], q8);
            int gbase = blockIdx.x*4 + nw*2;
#pragma unroll
            for (int g = 0; g < 2; g++) {
                gmax[(size_t)(gbase + g)*128 + r0]     = m0[g];
                gmax[(size_t)(gbase + g)*128 + r0 + 8] = m8[g];
            }
        }
    }
    __syncthreads();
    if (tid < NOUT) {
        atomicAdd(gsum + tid, s_sum[tid]);
        atomicAdd(gsq  + tid, s_sq[tid]);
    }
}

// ---------------- BN finalize ----------------
__global__ void finalize_kernel(int layer, const float* __restrict__ gamma,
                                const float* __restrict__ beta, int C) {
    int c = threadIdx.x;
    if (c >= C) return;
    float S = g_sum[layer*128 + c], Q = g_sq[layer*128 + c];
    float m = S * (1.f/524288.f);
    float var = Q * (1.f/524288.f) - m*m;
    float A = gamma[c] * rsqrtf(var + 1e-5f);
    g_a[layer*128 + c]  = A;
    g_bb[layer*128 + c] = beta[c] - m*A;
}

// ---------------- final: BN+ReLU of group-max, transposed store ----------------
__global__ void gfin_kernel(const float* __restrict__ gmax,
                            const float* __restrict__ A,
                            const float* __restrict__ B,
                            float* __restrict__ out) {
    __shared__ float t[32][33];
    int s0 = blockIdx.x*32, c0 = blockIdx.y*32, b = blockIdx.z;
    int tx = threadIdx.x, ty = threadIdx.y;
    for (int k = ty; k < 32; k += 8)
        t[k][tx] = gmax[(size_t)(b*1024 + s0 + k)*128 + c0 + tx];
    __syncthreads();
    for (int k = ty; k < 32; k += 8) {
        int c = c0 + k;
        float v = fmaxf(fmaf(t[tx][k], A[c], B[c]), 0.f);
        out[16*3*1024 + ((size_t)(b*128 + c))*1024 + s0 + tx] = v;
    }
}

// ---------------- launch ----------------
extern "C" void kernel_launch(void* const* d_in, const int* in_sizes, int n_in,
                              void* d_out, int out_size) {
    const float* xyz = (const float*)d_in[0];
    const float* pts = (const float*)d_in[1];
    const float* W0 = (const float*)d_in[2];
    const float* b0 = (const float*)d_in[3];
    const float* ga0 = (const float*)d_in[4];
    const float* be0 = (const float*)d_in[5];
    const float* W1 = (const float*)d_in[6];
    const float* b1 = (const float*)d_in[7];
    const float* ga1 = (const float*)d_in[8];
    const float* be1 = (const float*)d_in[9];
    const float* W2 = (const float*)d_in[10];
    const float* b2 = (const float*)d_in[11];
    const float* ga2 = (const float*)d_in[12];
    const float* be2 = (const float*)d_in[13];
    float* out = (float*)d_out;

    float *pY1, *pY2, *pGM, *pA, *pB, *pS, *pQ;
    uint32_t *pW2h, *pW2l, *pW3h, *pW3l;
    cudaGetSymbolAddress((void**)&pY1, g_Y1);
    cudaGetSymbolAddress((void**)&pY2, g_Y2);
    cudaGetSymbolAddress((void**)&pGM, g_gmax);
    cudaGetSymbolAddress((void**)&pA, g_a);
    cudaGetSymbolAddress((void**)&pB, g_bb);
    cudaGetSymbolAddress((void**)&pS, g_sum);
    cudaGetSymbolAddress((void**)&pQ, g_sq);
    cudaGetSymbolAddress((void**)&pW2h, g_W2h);
    cudaGetSymbolAddress((void**)&pW2l, g_W2l);
    cudaGetSymbolAddress((void**)&pW3h, g_W3h);
    cudaGetSymbolAddress((void**)&pW3l, g_W3l);

    const int smem1 = (2*128*44 + 2*64*44)*4 + 64*3*4;
    const int smem2 = (256*36 + 2*64*36)*4  + 64*3*4;
    const int smem3 = (256*36 + 2*128*36)*4 + 128*3*4;
    cudaFuncSetAttribute(mlp1_mma_kernel, cudaFuncAttributeMaxDynamicSharedMemorySize, smem1);
    cudaFuncSetAttribute(mlp2_mma_kernel, cudaFuncAttributeMaxDynamicSharedMemorySize, smem2);
    cudaFuncSetAttribute(mlp3_mma_kernel, cudaFuncAttributeMaxDynamicSharedMemorySize, smem3);

    wprep_kernel<<<16, 256>>>(W0, W1, W2);
    transpose_kernel<<<dim3(Nx/32, Dx/32, Bx), dim3(32, 32)>>>(pts);
    fps_kernel<<<Bx, 256>>>(xyz, out);      // also zeroes stats
    qb_kernel<<<Bx*Sx/8, 256>>>(xyz);

    mlp1_mma_kernel<<<Px/128, 256, smem1>>>(xyz, b0, pY1, pS + 0, pQ + 0);
    finalize_kernel<<<1, 128>>>(0, ga0, be0, 64);

    mlp2_mma_kernel<<<Px/128, 256, smem2>>>(pY1, pW2h, pW2l, b1, pA + 0, pB + 0,
                                            pY2, pS + 128, pQ + 128);
    finalize_kernel<<<1, 128>>>(1, ga1, be1, 64);

    mlp3_mma_kernel<<<Px/128, 256, smem3>>>(pY2, pW3h, pW3l, b2, pA + 128, pB + 128,
                                            pGM, pS + 256, pQ + 256);
    finalize_kernel<<<1, 128>>>(2, ga2, be2, 128);

    gfin_kernel<<<dim3(32, 4, 16), dim3(32, 8)>>>(pGM, pA + 256, pB + 256, out);
}

// round 16
// speedup vs baseline: 1.9474x; 1.0158x over previous
#include <cuda_runtime.h>
#include <cuda_fp16.h>
#include <cstdint>

#define Bx 16
#define Nx 4096
#define Sx 1024
#define Kx 32
#define Dx 64
#define Px (Bx*Sx*Kx)   // 524288

typedef unsigned long long ull;

// ---------------- device scratch ----------------
__device__ float g_centers[Bx*Sx*3];
__device__ int   g_gidx[Bx*Sx*Kx];
__device__ float g_ptsT[Bx*Nx*Dx];
__device__ float g_Y1[64u*Px];          // channel-major
__device__ float g_Y2[64u*Px];          // channel-major
__device__ float g_gmax[Bx*Sx*128];     // [group][c] raw max of layer3 pre-BN
__device__ uint32_t g_W1h[64*40];
__device__ uint32_t g_W1l[64*40];
__device__ uint32_t g_W2h[64*32];
__device__ uint32_t g_W2l[64*32];
__device__ uint32_t g_W3h[128*32];
__device__ uint32_t g_W3l[128*32];
__device__ float g_sum[384];
__device__ float g_sq[384];
__device__ float g_a[384];
__device__ float g_bb[384];

// ---------------- helpers ----------------
__device__ __forceinline__ uint32_t packh2(float a, float b) {
    __half2 h = __halves2half2(__float2half_rn(a), __float2half_rn(b));
    return *reinterpret_cast<uint32_t*>(&h);
}
__device__ __forceinline__ void split2(float a, float b, uint32_t &hi, uint32_t &lo) {
    __half h0 = __float2half_rn(a), h1 = __float2half_rn(b);
    __half2 hh = __halves2half2(h0, h1);
    hi = *reinterpret_cast<uint32_t*>(&hh);
    lo = packh2(a - __half2float(h0), b - __half2float(h1));
}
__device__ __forceinline__ void mma16816(float* d, const uint32_t* a, const uint32_t* b) {
    asm volatile(
        "mma.sync.aligned.m16n8k16.row.col.f32.f16.f16.f32 "
        "{%0,%1,%2,%3}, {%4,%5,%6,%7}, {%8,%9}, {%0,%1,%2,%3};"
        : "+f"(d[0]), "+f"(d[1]), "+f"(d[2]), "+f"(d[3])
        : "r"(a[0]), "r"(a[1]), "r"(a[2]), "r"(a[3]), "r"(b[0]), "r"(b[1]));
}
__device__ __forceinline__ uint32_t sm_u32(const void* p) {
    return (uint32_t)__cvta_generic_to_shared(p);
}
__device__ __forceinline__ void ldsm4(uint32_t* r, uint32_t addr) {
    asm volatile("ldmatrix.sync.aligned.m8n8.x4.shared.b16 {%0,%1,%2,%3}, [%4];"
        : "=r"(r[0]), "=r"(r[1]), "=r"(r[2]), "=r"(r[3]) : "r"(addr));
}
__device__ __forceinline__ ull packf2(float lo, float hi) {
    ull r; asm("mov.b64 %0, {%1, %2};" : "=l"(r) : "f"(lo), "f"(hi)); return r;
}
__device__ __forceinline__ float2 unpackf2(ull v) {
    float lo, hi; asm("mov.b64 {%0, %1}, %2;" : "=f"(lo), "=f"(hi) : "l"(v));
    return make_float2(lo, hi);
}
__device__ __forceinline__ ull add2(ull a, ull b) {
    ull r; asm("add.rn.f32x2 %0, %1, %2;" : "=l"(r) : "l"(a), "l"(b)); return r;
}
__device__ __forceinline__ ull mul2(ull a, ull b) {
    ull r; asm("mul.rn.f32x2 %0, %1, %2;" : "=l"(r) : "l"(a), "l"(b)); return r;
}
__device__ __forceinline__ ull fma2v(ull a, ull b, ull c) {
    ull r; asm("fma.rn.f32x2 %0, %1, %2, %3;" : "=l"(r) : "l"(a), "l"(b), "l"(c)); return r;
}

// ---------------- zero stats ----------------
__global__ void zstats_kernel() {
    int t = blockIdx.x*256 + threadIdx.x;
    if (t < 384) { g_sum[t] = 0.f; g_sq[t] = 0.f; }
}

// ---------------- transpose points (B,64,N) -> ptsT (B,N,64) ----------------
__global__ void transpose_kernel(const float* __restrict__ pts) {
    __shared__ float tile[32][33];
    int b = blockIdx.z, n0 = blockIdx.x*32, d0 = blockIdx.y*32;
    int tx = threadIdx.x, ty = threadIdx.y;
    tile[ty][tx] = pts[((size_t)b*Dx + d0 + ty)*Nx + n0 + tx];
    __syncthreads();
    g_ptsT[((size_t)b*Nx + n0 + ty)*Dx + d0 + tx] = tile[tx][ty];
}

// ---------------- weight split prep (all 3 layers) ----------------
__global__ void wprep_kernel(const float* __restrict__ W0,
                             const float* __restrict__ W1,
                             const float* __restrict__ W2) {
    int i = blockIdx.x*256 + threadIdx.x;
    if (i < 64*40) {
        int o = i / 40, c2 = i % 40;
        float w[2];
#pragma unroll
        for (int j = 0; j < 2; j++) {
            int ch = 2*c2 + j;
            if (ch < 64)      w[j] = W0[o*67 + 3 + ch];
            else if (ch < 67) w[j] = W0[o*67 + (ch - 64)];
            else              w[j] = 0.f;
        }
        split2(w[0], w[1], g_W1h[i], g_W1l[i]);
    }
    if (i < 64*32) {
        int o = i >> 5, c2 = i & 31;
        split2(W1[o*64 + 2*c2], W1[o*64 + 2*c2 + 1], g_W2h[i], g_W2l[i]);
    }
    if (i < 128*32) {
        int o = i >> 5, c2 = i & 31;
        split2(W2[o*64 + 2*c2], W2[o*64 + 2*c2 + 1], g_W3h[i], g_W3l[i]);
    }
}

// ---------------- FPS: 512 thr x 8 pts, redux final reduce ----------------
__global__ __launch_bounds__(512) void fps_kernel(const float* __restrict__ xyz,
                                                  float* __restrict__ out) {
    int b = blockIdx.x, t = threadIdx.x;
    int lane = t & 31, w = t >> 5;        // 16 warps
    const float* xb = xyz + (size_t)b*3*Nx;
    // 8 pts as 4 pairs: pair j = (n0 = j*1024 + t, n0 + 512); ascending n order
    ull px2[4], py2[4], pz2[4], dst2[4];
#pragma unroll
    for (int j = 0; j < 4; j++) {
        int n = j*1024 + t;
        px2[j] = packf2(xb[n],      xb[n + 512]);
        py2[j] = packf2(xb[Nx+n],   xb[Nx+n + 512]);
        pz2[j] = packf2(xb[2*Nx+n], xb[2*Nx+n + 512]);
        dst2[j] = packf2(1e10f, 1e10f);
    }
    __shared__ ull s_red[2][16];
    int far = 0;
    for (int s = 0; s < Sx; s++) {
        float cx = __ldg(xb + far), cy = __ldg(xb + Nx + far), cz = __ldg(xb + 2*Nx + far);
        if (t == 0) {
            out[b*3*Sx + s] = cx; out[b*3*Sx + Sx + s] = cy; out[b*3*Sx + 2*Sx + s] = cz;
        }
        if (t == 32) {   // warp 1: centers for qb/mlp1 (identical values)
            g_centers[(b*Sx+s)*3+0] = cx; g_centers[(b*Sx+s)*3+1] = cy; g_centers[(b*Sx+s)*3+2] = cz;
        }
        ull ncx = packf2(-cx, -cx), ncy = packf2(-cy, -cy), ncz = packf2(-cz, -cz);
        float best = -1.f; int bn = 0;
#pragma unroll
        for (int j = 0; j < 4; j++) {
            ull dx = add2(px2[j], ncx);
            ull dy = add2(py2[j], ncy);
            ull dz = add2(pz2[j], ncz);
            ull d  = mul2(dx, dx);
            d = fma2v(dy, dy, d);
            d = fma2v(dz, dz, d);
            float2 df = unpackf2(d);
            float2 ds = unpackf2(dst2[j]);
            float nd0 = fminf(ds.x, df.x);
            float nd1 = fminf(ds.y, df.y);
            dst2[j] = packf2(nd0, nd1);
            int n0 = j*1024 + t;
            if (nd0 > best) { best = nd0; bn = n0; }          // ascending n, strict >
            if (nd1 > best) { best = nd1; bn = n0 + 512; }
        }
        unsigned ub = __float_as_uint(best);                   // dist>=0: bits order-isomorphic
        unsigned wmax = __reduce_max_sync(0xffffffffu, ub);
        unsigned cand = (ub == wmax) ? (unsigned)bn : 0xffffffffu;
        unsigned bmin = __reduce_min_sync(0xffffffffu, cand);
        if (lane == 0)
            s_red[s & 1][w] = ((ull)wmax << 32) | (unsigned)(0x7FFFFFFF - (int)bmin);
        __syncthreads();
        ull k = s_red[s & 1][lane & 15];
        unsigned hi = (unsigned)(k >> 32), lo = (unsigned)k;
        unsigned hm = __reduce_max_sync(0xffffffffu, hi);      // max dist
        unsigned cl = (hi == hm) ? lo : 0u;                    // lo = 0x7fffffff - idx > 0
        unsigned lm = __reduce_max_sync(0xffffffffu, cl);      // max lo = min idx
        far = 0x7FFFFFFF - (int)lm;
    }
}

// ---------------- ball query (R8 proven) ----------------
__global__ __launch_bounds__(256) void qb_kernel(const float* __restrict__ xyz) {
    int blk = blockIdx.x;
    int b = blk >> 7;
    int w = threadIdx.x >> 5;
    int s = (blk & 127)*8 + w;
    int lane = threadIdx.x & 31;
    __shared__ int buf[8][32];
    const float* xb = xyz + (size_t)b*3*Nx;
    float cx = g_centers[(b*Sx+s)*3+0], cy = g_centers[(b*Sx+s)*3+1], cz = g_centers[(b*Sx+s)*3+2];
    float s2 = (cx*cx + cy*cy) + cz*cz;
    int cnt = 0;
    for (int base = 0; base < Nx; base += 128) {
        int n0 = base + lane*4;
        float4 X4 = *reinterpret_cast<const float4*>(xb + n0);
        float4 Y4 = *reinterpret_cast<const float4*>(xb + Nx + n0);
        float4 Z4 = *reinterpret_cast<const float4*>(xb + 2*Nx + n0);
        unsigned msk = 0;
        { float dot = (cx*X4.x + cy*Y4.x) + cz*Z4.x; float d2 = (X4.x*X4.x + Y4.x*Y4.x) + Z4.x*Z4.x;
          float d = -2.f*dot; d += s2; d += d2; if (!(d > 0.01f)) msk |= 1u; }
        { float dot = (cx*X4.y + cy*Y4.y) + cz*Z4.y; float d2 = (X4.y*X4.y + Y4.y*Y4.y) + Z4.y*Z4.y;
          float d = -2.f*dot; d += s2; d += d2; if (!(d > 0.01f)) msk |= 2u; }
        { float dot = (cx*X4.z + cy*Y4.z) + cz*Z4.z; float d2 = (X4.z*X4.z + Y4.z*Y4.z) + Z4.z*Z4.z;
          float d = -2.f*dot; d += s2; d += d2; if (!(d > 0.01f)) msk |= 4u; }
        { float dot = (cx*X4.w + cy*Y4.w) + cz*Z4.w; float d2 = (X4.w*X4.w + Y4.w*Y4.w) + Z4.w*Z4.w;
          float d = -2.f*dot; d += s2; d += d2; if (!(d > 0.01f)) msk |= 8u; }
        int tc = __popc(msk);
        int inc = tc;
#pragma unroll
        for (int d = 1; d < 32; d <<= 1) {
            int v = __shfl_up_sync(0xffffffffu, inc, d);
            if (lane >= d) inc += v;
        }
        int excl = inc - tc;
        int total = __shfl_sync(0xffffffffu, inc, 31);
        int pos = cnt + excl;
#pragma unroll
        for (int j = 0; j < 4; j++) {
            if (msk & (1u << j)) { if (pos < Kx) buf[w][pos] = n0 + j; pos++; }
        }
        cnt += total;
        if (cnt >= Kx) break;
    }
    __syncwarp();
    int nv = cnt < Kx ? cnt : Kx;
    int first = buf[w][0];
    int v = (lane < nv) ? buf[w][lane] : first;
    g_gidx[(b*Sx + s)*Kx + lane] = v;
}

// ================= layer 1: gather + mma.sync fp16-split (K=80), ldmatrix =====
__global__ __launch_bounds__(256) void mlp1_mma_kernel(const float* __restrict__ xyz,
                                                       const float* __restrict__ bias,
                                                       float* __restrict__ Y,
                                                       float* __restrict__ gsum,
                                                       float* __restrict__ gsq) {
    constexpr int PITCH = 44;
    constexpr int NOUT = 64;
    constexpr int MW = 2, NFR = 4;
    extern __shared__ uint32_t sm[];
    uint32_t* s_xh = sm;
    uint32_t* s_xl = sm + 128*PITCH;
    uint32_t* s_wh = sm + 256*PITCH;
    uint32_t* s_wl = s_wh + NOUT*PITCH;
    float* s_bias = reinterpret_cast<float*>(s_wl + NOUT*PITCH);
    float* s_sum = s_bias + NOUT;
    float* s_sq  = s_sum + NOUT;

    int tid = threadIdx.x;
    int wid = tid >> 5, lane = tid & 31;
    int qr = lane >> 2, qc = lane & 3;
    size_t p0 = (size_t)blockIdx.x * 128;

    if (tid < NOUT) { s_bias[tid] = bias[tid]; s_sum[tid] = 0.f; s_sq[tid] = 0.f; }
    for (int i = tid; i < NOUT*40; i += 256) {
        int o = i / 40, c2 = i % 40;
        s_wh[o*PITCH + c2] = g_W1h[i];
        s_wl[o*PITCH + c2] = g_W1l[i];
    }
    {
        int p = tid >> 1, h = tid & 1;
        size_t pp = p0 + p;
        int bs = (int)(pp >> 5);
        int b = bs >> 10;
        int idx = g_gidx[pp];
        const float4* row = reinterpret_cast<const float4*>(g_ptsT + ((size_t)b*Nx + idx)*Dx) + h*8;
#pragma unroll
        for (int j = 0; j < 8; j++) {
            float4 v = row[j];
            int c2 = h*16 + 2*j;
            split2(v.x, v.y, s_xh[p*PITCH + c2],     s_xl[p*PITCH + c2]);
            split2(v.z, v.w, s_xh[p*PITCH + c2 + 1], s_xl[p*PITCH + c2 + 1]);
        }
        if (h == 1) {
            float cx = g_centers[bs*3+0], cy = g_centers[bs*3+1], cz = g_centers[bs*3+2];
            const float* xb = xyz + (size_t)b*3*Nx;
            float dx = __ldg(xb + idx)        - cx;
            float dy = __ldg(xb + Nx + idx)   - cy;
            float dz = __ldg(xb + 2*Nx + idx) - cz;
            split2(dx, dy, s_xh[p*PITCH + 32], s_xl[p*PITCH + 32]);
            split2(dz, 0.f, s_xh[p*PITCH + 33], s_xl[p*PITCH + 33]);
#pragma unroll
            for (int c2 = 34; c2 < 40; c2++) { s_xh[p*PITCH + c2] = 0u; s_xl[p*PITCH + c2] = 0u; }
        }
    }
    __syncthreads();

    int mw = wid % MW, nw = wid / MW;
    int mbase = mw * 32;
    int pbase = nw * 32;

    int tile = lane >> 3, tr = lane & 7;
    uint32_t aoff = (uint32_t)(((mbase + tr + ((tile & 1) << 3))*PITCH + ((tile >> 1) << 2)) * 4);
    uint32_t boff = (uint32_t)(((pbase + ((tile >> 1) << 3) + tr)*PITCH + ((tile & 1) << 2)) * 4);

    float d[2][NFR][4];
#pragma unroll
    for (int mf = 0; mf < 2; mf++)
#pragma unroll
        for (int nf = 0; nf < NFR; nf++)
#pragma unroll
            for (int j = 0; j < 4; j++) d[mf][nf][j] = 0.f;

#pragma unroll
    for (int pass = 0; pass < 3; pass++) {
        const uint32_t* wsrc = (pass == 2) ? s_wl : s_wh;
        const uint32_t* xsrc = (pass == 1) ? s_xl : s_xh;
        uint32_t abase = sm_u32(wsrc) + aoff;
        uint32_t bbase = sm_u32(xsrc) + boff;
#pragma unroll
        for (int ks = 0; ks < 5; ks++) {
            uint32_t a0[4], a1[4];
            ldsm4(a0, abase);
            ldsm4(a1, abase + (uint32_t)(16*PITCH*4));
            uint32_t bf[NFR][2];
#pragma unroll
            for (int np = 0; np < NFR/2; np++) {
                uint32_t r4[4];
                ldsm4(r4, bbase + (uint32_t)(np*16*PITCH*4));
                bf[2*np][0] = r4[0]; bf[2*np][1] = r4[1];
                bf[2*np+1][0] = r4[2]; bf[2*np+1][1] = r4[3];
            }
#pragma unroll
            for (int nf = 0; nf < NFR; nf++) mma16816(d[0][nf], a0, bf[nf]);
#pragma unroll
            for (int nf = 0; nf < NFR; nf++) mma16816(d[1][nf], a1, bf[nf]);
            abase += 32; bbase += 32;
        }
    }

#pragma unroll
    for (int mf = 0; mf < 2; mf++) {
        int r0 = mbase + mf*16 + qr;
        float b0 = s_bias[r0], b8 = s_bias[r0 + 8];
        float s0 = 0.f, q0 = 0.f, s8 = 0.f, q8 = 0.f;
#pragma unroll
        for (int nf = 0; nf < NFR; nf++) {
            int p = pbase + nf*8 + 2*qc;
            float y0 = d[mf][nf][0] + b0, y1 = d[mf][nf][1] + b0;
            float y2 = d[mf][nf][2] + b8, y3 = d[mf][nf][3] + b8;
            *reinterpret_cast<float2*>(Y + (size_t)r0*Px + p0 + p)     = make_float2(y0, y1);
            *reinterpret_cast<float2*>(Y + (size_t)(r0+8)*Px + p0 + p) = make_float2(y2, y3);
            s0 += y0 + y1; q0 += y0*y0 + y1*y1;
            s8 += y2 + y3; q8 += y2*y2 + y3*y3;
        }
        s0 += __shfl_xor_sync(0xffffffffu, s0, 1); s0 += __shfl_xor_sync(0xffffffffu, s0, 2);
        q0 += __shfl_xor_sync(0xffffffffu, q0, 1); q0 += __shfl_xor_sync(0xffffffffu, q0, 2);
        s8 += __shfl_xor_sync(0xffffffffu, s8, 1); s8 += __shfl_xor_sync(0xffffffffu, s8, 2);
        q8 += __shfl_xor_sync(0xffffffffu, q8, 1); q8 += __shfl_xor_sync(0xffffffffu, q8, 2);
        if (qc == 0) {
            atomicAdd(&s_sum[r0], s0);     atomicAdd(&s_sq[r0], q0);
            atomicAdd(&s_sum[r0 + 8], s8); atomicAdd(&s_sq[r0 + 8], q8);
        }
    }
    __syncthreads();
    if (tid < NOUT) {
        atomicAdd(gsum + tid, s_sum[tid]);
        atomicAdd(gsq  + tid, s_sq[tid]);
    }
}

// ================= layer 2: mma.sync fp16-split, ldmatrix, occ=3 =================
__global__ __launch_bounds__(256, 3) void mlp2_mma_kernel(const float* __restrict__ X,
                                                       const uint32_t* __restrict__ Wh,
                                                       const uint32_t* __restrict__ Wl,
                                                       const float* __restrict__ bias,
                                                       const float* __restrict__ Aarr,
                                                       const float* __restrict__ Barr,
                                                       float* __restrict__ Y,
                                                       float* __restrict__ gsum,
                                                       float* __restrict__ gsq) {
    constexpr int PITCH = 36;
    constexpr int NOUT = 64;
    constexpr int MW = 2, NFR = 4;
    extern __shared__ uint32_t sm[];
    uint32_t* s_xh = sm;
    uint32_t* s_xl = sm + 128*PITCH;
    uint32_t* s_wh = sm + 256*PITCH;
    uint32_t* s_wl = s_wh + NOUT*PITCH;
    float* s_bias = reinterpret_cast<float*>(s_wl + NOUT*PITCH);
    float* s_sum = s_bias + NOUT;
    float* s_sq  = s_sum + NOUT;

    int tid = threadIdx.x;
    int wid = tid >> 5, lane = tid & 31;
    int qr = lane >> 2, qc = lane & 3;
    size_t p0 = (size_t)blockIdx.x * 128;

    if (tid < NOUT) { s_bias[tid] = bias[tid]; s_sum[tid] = 0.f; s_sq[tid] = 0.f; }
    for (int i = tid; i < NOUT*32; i += 256) {
        int o = i >> 5, c2 = i & 31;
        s_wh[o*PITCH + c2] = Wh[i];
        s_wl[o*PITCH + c2] = Wl[i];
    }
    {
        int p = tid & 127;
        int ch0 = (tid >> 7) * 32;
#pragma unroll
        for (int j = 0; j < 16; j++) {
            int c = ch0 + 2*j;
            float v0 = X[(size_t)c*Px + p0 + p];
            float v1 = X[(size_t)(c+1)*Px + p0 + p];
            v0 = fmaxf(fmaf(v0, Aarr[c],   Barr[c]),   0.f);
            v1 = fmaxf(fmaf(v1, Aarr[c+1], Barr[c+1]), 0.f);
            split2(v0, v1, s_xh[p*PITCH + (c >> 1)], s_xl[p*PITCH + (c >> 1)]);
        }
    }
    __syncthreads();

    int mw = wid % MW, nw = wid / MW;
    int mbase = mw * 32;
    int pbase = nw * 32;

    int tile = lane >> 3, tr = lane & 7;
    uint32_t aoff = (uint32_t)(((mbase + tr + ((tile & 1) << 3))*PITCH + ((tile >> 1) << 2)) * 4);
    uint32_t boff = (uint32_t)(((pbase + ((tile >> 1) << 3) + tr)*PITCH + ((tile & 1) << 2)) * 4);

    float d[2][NFR][4];
#pragma unroll
    for (int mf = 0; mf < 2; mf++)
#pragma unroll
        for (int nf = 0; nf < NFR; nf++)
#pragma unroll
            for (int j = 0; j < 4; j++) d[mf][nf][j] = 0.f;

#pragma unroll
    for (int pass = 0; pass < 3; pass++) {
        const uint32_t* wsrc = (pass == 2) ? s_wl : s_wh;
        const uint32_t* xsrc = (pass == 1) ? s_xl : s_xh;
        uint32_t abase = sm_u32(wsrc) + aoff;
        uint32_t bbase = sm_u32(xsrc) + boff;
#pragma unroll
        for (int ks = 0; ks < 4; ks++) {
            uint32_t a0[4], a1[4];
            ldsm4(a0, abase);
            ldsm4(a1, abase + (uint32_t)(16*PITCH*4));
            uint32_t bf[NFR][2];
#pragma unroll
            for (int np = 0; np < NFR/2; np++) {
                uint32_t r4[4];
                ldsm4(r4, bbase + (uint32_t)(np*16*PITCH*4));
                bf[2*np][0] = r4[0]; bf[2*np][1] = r4[1];
                bf[2*np+1][0] = r4[2]; bf[2*np+1][1] = r4[3];
            }
#pragma unroll
            for (int nf = 0; nf < NFR; nf++) mma16816(d[0][nf], a0, bf[nf]);
#pragma unroll
            for (int nf = 0; nf < NFR; nf++) mma16816(d[1][nf], a1, bf[nf]);
            abase += 32; bbase += 32;
        }
    }

#pragma unroll
    for (int mf = 0; mf < 2; mf++) {
        int r0 = mbase + mf*16 + qr;
        float b0 = s_bias[r0], b8 = s_bias[r0 + 8];
        float s0 = 0.f, q0 = 0.f, s8 = 0.f, q8 = 0.f;
#pragma unroll
        for (int nf = 0; nf < NFR; nf++) {
            int p = pbase + nf*8 + 2*qc;
            float y0 = d[mf][nf][0] + b0, y1 = d[mf][nf][1] + b0;
            float y2 = d[mf][nf][2] + b8, y3 = d[mf][nf][3] + b8;
            *reinterpret_cast<float2*>(Y + (size_t)r0*Px + p0 + p)     = make_float2(y0, y1);
            *reinterpret_cast<float2*>(Y + (size_t)(r0+8)*Px + p0 + p) = make_float2(y2, y3);
            s0 += y0 + y1; q0 += y0*y0 + y1*y1;
            s8 += y2 + y3; q8 += y2*y2 + y3*y3;
        }
        s0 += __shfl_xor_sync(0xffffffffu, s0, 1); s0 += __shfl_xor_sync(0xffffffffu, s0, 2);
        q0 += __shfl_xor_sync(0xffffffffu, q0, 1); q0 += __shfl_xor_sync(0xffffffffu, q0, 2);
        s8 += __shfl_xor_sync(0xffffffffu, s8, 1); s8 += __shfl_xor_sync(0xffffffffu, s8, 2);
        q8 += __shfl_xor_sync(0xffffffffu, q8, 1); q8 += __shfl_xor_sync(0xffffffffu, q8, 2);
        if (qc == 0) {
            atomicAdd(&s_sum[r0], s0);     atomicAdd(&s_sq[r0], q0);
            atomicAdd(&s_sum[r0 + 8], s8); atomicAdd(&s_sq[r0 + 8], q8);
        }
    }
    __syncthreads();
    if (tid < NOUT) {
        atomicAdd(gsum + tid, s_sum[tid]);
        atomicAdd(gsq  + tid, s_sq[tid]);
    }
}

// ================= layer 3: ldmatrix, stats + in-register group-max ===========
__global__ __launch_bounds__(256) void mlp3_mma_kernel(const float* __restrict__ X,
                                                       const uint32_t* __restrict__ Wh,
                                                       const uint32_t* __restrict__ Wl,
                                                       const float* __restrict__ bias,
                                                       const float* __restrict__ Aarr,
                                                       const float* __restrict__ Barr,
                                                       float* __restrict__ gmax,
                                                       float* __restrict__ gsum,
                                                       float* __restrict__ gsq) {
    constexpr int PITCH = 36;
    constexpr int NOUT = 128;
    constexpr int MW = 4, NFR = 8;
    extern __shared__ uint32_t sm[];
    uint32_t* s_xh = sm;
    uint32_t* s_xl = sm + 128*PITCH;
    uint32_t* s_wh = sm + 256*PITCH;
    uint32_t* s_wl = s_wh + NOUT*PITCH;
    float* s_bias = reinterpret_cast<float*>(s_wl + NOUT*PITCH);
    float* s_sum = s_bias + NOUT;
    float* s_sq  = s_sum + NOUT;

    int tid = threadIdx.x;
    int wid = tid >> 5, lane = tid & 31;
    int qr = lane >> 2, qc = lane & 3;
    size_t p0 = (size_t)blockIdx.x * 128;

    if (tid < NOUT) { s_bias[tid] = bias[tid]; s_sum[tid] = 0.f; s_sq[tid] = 0.f; }
    for (int i = tid; i < NOUT*32; i += 256) {
        int o = i >> 5, c2 = i & 31;
        s_wh[o*PITCH + c2] = Wh[i];
        s_wl[o*PITCH + c2] = Wl[i];
    }
    {
        int p = tid & 127;
        int ch0 = (tid >> 7) * 32;
#pragma unroll
        for (int j = 0; j < 16; j++) {
            int c = ch0 + 2*j;
            float v0 = X[(size_t)c*Px + p0 + p];
            float v1 = X[(size_t)(c+1)*Px + p0 + p];
            v0 = fmaxf(fmaf(v0, Aarr[c],   Barr[c]),   0.f);
            v1 = fmaxf(fmaf(v1, Aarr[c+1], Barr[c+1]), 0.f);
            split2(v0, v1, s_xh[p*PITCH + (c >> 1)], s_xl[p*PITCH + (c >> 1)]);
        }
    }
    __syncthreads();

    int mw = wid % MW, nw = wid / MW;
    int mbase = mw * 32;
    int pbase = nw * 64;

    int tile = lane >> 3, tr = lane & 7;
    uint32_t aoff = (uint32_t)(((mbase + tr + ((tile & 1) << 3))*PITCH + ((tile >> 1) << 2)) * 4);
    uint32_t boff = (uint32_t)(((pbase + ((tile >> 1) << 3) + tr)*PITCH + ((tile & 1) << 2)) * 4);

    float d[2][NFR][4];
#pragma unroll
    for (int mf = 0; mf < 2; mf++)
#pragma unroll
        for (int nf = 0; nf < NFR; nf++)
#pragma unroll
            for (int j = 0; j < 4; j++) d[mf][nf][j] = 0.f;

#pragma unroll
    for (int pass = 0; pass < 3; pass++) {
        const uint32_t* wsrc = (pass == 2) ? s_wl : s_wh;
        const uint32_t* xsrc = (pass == 1) ? s_xl : s_xh;
        uint32_t abase = sm_u32(wsrc) + aoff;
        uint32_t bbase = sm_u32(xsrc) + boff;
#pragma unroll
        for (int ks = 0; ks < 4; ks++) {
            uint32_t a0[4], a1[4];
            ldsm4(a0, abase);
            ldsm4(a1, abase + (uint32_t)(16*PITCH*4));
            uint32_t bf[NFR][2];
#pragma unroll
            for (int np = 0; np < NFR/2; np++) {
                uint32_t r4[4];
                ldsm4(r4, bbase + (uint32_t)(np*16*PITCH*4));
                bf[2*np][0] = r4[0]; bf[2*np][1] = r4[1];
                bf[2*np+1][0] = r4[2]; bf[2*np+1][1] = r4[3];
            }
#pragma unroll
            for (int nf = 0; nf < NFR; nf++) mma16816(d[0][nf], a0, bf[nf]);
#pragma unroll
            for (int nf = 0; nf < NFR; nf++) mma16816(d[1][nf], a1, bf[nf]);
            abase += 32; bbase += 32;
        }
    }

#pragma unroll
    for (int mf = 0; mf < 2; mf++) {
        int r0 = mbase + mf*16 + qr;
        float b0 = s_bias[r0], b8 = s_bias[r0 + 8];
        float s0 = 0.f, q0 = 0.f, s8 = 0.f, q8 = 0.f;
        float m0[2] = {-3.4e38f, -3.4e38f};
        float m8[2] = {-3.4e38f, -3.4e38f};
#pragma unroll
        for (int nf = 0; nf < NFR; nf++) {
            int g = nf >> 2;
            float y0 = d[mf][nf][0] + b0, y1 = d[mf][nf][1] + b0;
            float y2 = d[mf][nf][2] + b8, y3 = d[mf][nf][3] + b8;
            s0 += y0 + y1; q0 += y0*y0 + y1*y1;
            s8 += y2 + y3; q8 += y2*y2 + y3*y3;
            m0[g] = fmaxf(m0[g], fmaxf(y0, y1));
            m8[g] = fmaxf(m8[g], fmaxf(y2, y3));
        }
        s0 += __shfl_xor_sync(0xffffffffu, s0, 1); s0 += __shfl_xor_sync(0xffffffffu, s0, 2);
        q0 += __shfl_xor_sync(0xffffffffu, q0, 1); q0 += __shfl_xor_sync(0xffffffffu, q0, 2);
        s8 += __shfl_xor_sync(0xffffffffu, s8, 1); s8 += __shfl_xor_sync(0xffffffffu, s8, 2);
        q8 += __shfl_xor_sync(0xffffffffu, q8, 1); q8 += __shfl_xor_sync(0xffffffffu, q8, 2);
#pragma unroll
        for (int g = 0; g < 2; g++) {
            m0[g] = fmaxf(m0[g], __shfl_xor_sync(0xffffffffu, m0[g], 1));
            m0[g] = fmaxf(m0[g], __shfl_xor_sync(0xffffffffu, m0[g], 2));
            m8[g] = fmaxf(m8[g], __shfl_xor_sync(0xffffffffu, m8[g], 1));
            m8[g] = fmaxf(m8[g], __shfl_xor_sync(0xffffffffu, m8[g], 2));
        }
        if (qc == 0) {
            atomicAdd(&s_sum[r0], s0);     atomicAdd(&s_sq[r0], q0);
            atomicAdd(&s_sum[r0 + 8], s8); atomicAdd(&s_sq[r0 + 8], q8);
            int gbase = blockIdx.x*4 + nw*2;
#pragma unroll
            for (int g = 0; g < 2; g++) {
                gmax[(size_t)(gbase + g)*128 + r0]     = m0[g];
                gmax[(size_t)(gbase + g)*128 + r0 + 8] = m8[g];
            }
        }
    }
    __syncthreads();
    if (tid < NOUT) {
        atomicAdd(gsum + tid, s_sum[tid]);
        atomicAdd(gsq  + tid, s_sq[tid]);
    }
}

// ---------------- BN finalize ----------------
__global__ void finalize_kernel(int layer, const float* __restrict__ gamma,
                                const float* __restrict__ beta, int C) {
    int c = threadIdx.x;
    if (c >= C) return;
    float S = g_sum[layer*128 + c], Q = g_sq[layer*128 + c];
    float m = S * (1.f/524288.f);
    float var = Q * (1.f/524288.f) - m*m;
    float A = gamma[c] * rsqrtf(var + 1e-5f);
    g_a[layer*128 + c]  = A;
    g_bb[layer*128 + c] = beta[c] - m*A;
}

// ---------------- final: BN+ReLU of group-max, transposed store ----------------
__global__ void gfin_kernel(const float* __restrict__ gmax,
                            const float* __restrict__ A,
                            const float* __restrict__ B,
                            float* __restrict__ out) {
    __shared__ float t[32][33];
    int s0 = blockIdx.x*32, c0 = blockIdx.y*32, b = blockIdx.z;
    int tx = threadIdx.x, ty = threadIdx.y;
    for (int k = ty; k < 32; k += 8)
        t[k][tx] = gmax[(size_t)(b*1024 + s0 + k)*128 + c0 + tx];
    __syncthreads();
    for (int k = ty; k < 32; k += 8) {
        int c = c0 + k;
        float v = fmaxf(fmaf(t[tx][k], A[c], B[c]), 0.f);
        out[16*3*1024 + ((size_t)(b*128 + c))*1024 + s0 + tx] = v;
    }
}

// ---------------- launch ----------------
extern "C" void kernel_launch(void* const* d_in, const int* in_sizes, int n_in,
                              void* d_out, int out_size) {
    const float* xyz = (const float*)d_in[0];
    const float* pts = (const float*)d_in[1];
    const float* W0 = (const float*)d_in[2];
    const float* b0 = (const float*)d_in[3];
    const float* ga0 = (const float*)d_in[4];
    const float* be0 = (const float*)d_in[5];
    const float* W1 = (const float*)d_in[6];
    const float* b1 = (const float*)d_in[7];
    const float* ga1 = (const float*)d_in[8];
    const float* be1 = (const float*)d_in[9];
    const float* W2 = (const float*)d_in[10];
    const float* b2 = (const float*)d_in[11];
    const float* ga2 = (const float*)d_in[12];
    const float* be2 = (const float*)d_in[13];
    float* out = (float*)d_out;

    float *pY1, *pY2, *pGM, *pA, *pB, *pS, *pQ;
    uint32_t *pW2h, *pW2l, *pW3h, *pW3l;
    cudaGetSymbolAddress((void**)&pY1, g_Y1);
    cudaGetSymbolAddress((void**)&pY2, g_Y2);
    cudaGetSymbolAddress((void**)&pGM, g_gmax);
    cudaGetSymbolAddress((void**)&pA, g_a);
    cudaGetSymbolAddress((void**)&pB, g_bb);
    cudaGetSymbolAddress((void**)&pS, g_sum);
    cudaGetSymbolAddress((void**)&pQ, g_sq);
    cudaGetSymbolAddress((void**)&pW2h, g_W2h);
    cudaGetSymbolAddress((void**)&pW2l, g_W2l);
    cudaGetSymbolAddress((void**)&pW3h, g_W3h);
    cudaGetSymbolAddress((void**)&pW3l, g_W3l);

    const int smem1 = (2*128*44 + 2*64*44)*4 + 64*3*4;
    const int smem2 = (256*36 + 2*64*36)*4  + 64*3*4;
    const int smem3 = (256*36 + 2*128*36)*4 + 128*3*4;
    cudaFuncSetAttribute(mlp1_mma_kernel, cudaFuncAttributeMaxDynamicSharedMemorySize, smem1);
    cudaFuncSetAttribute(mlp2_mma_kernel, cudaFuncAttributeMaxDynamicSharedMemorySize, smem2);
    cudaFuncSetAttribute(mlp3_mma_kernel, cudaFuncAttributeMaxDynamicSharedMemorySize, smem3);

    zstats_kernel<<<2, 256>>>();                                       // 1
    wprep_kernel<<<16, 256>>>(W0, W1, W2);                             // 2
    transpose_kernel<<<dim3(Nx/32, Dx/32, Bx), dim3(32, 32)>>>(pts);   // 3
    fps_kernel<<<Bx, 512>>>(xyz, out);                                 // 4 (captured)
    qb_kernel<<<Bx*Sx/8, 256>>>(xyz);

    mlp1_mma_kernel<<<Px/128, 256, smem1>>>(xyz, b0, pY1, pS + 0, pQ + 0);
    finalize_kernel<<<1, 128>>>(0, ga0, be0, 64);

    mlp2_mma_kernel<<<Px/128, 256, smem2>>>(pY1, pW2h, pW2l, b1, pA + 0, pB + 0,
                                            pY2, pS + 128, pQ + 128);
    finalize_kernel<<<1, 128>>>(1, ga1, be1, 64);

    mlp3_mma_kernel<<<Px/128, 256, smem3>>>(pY2, pW3h, pW3l, b2, pA + 128, pB + 128,
                                            pGM, pS + 256, pQ + 256);
    finalize_kernel<<<1, 128>>>(2, ga2, be2, 128);

    gfin_kernel<<<dim3(32, 4, 16), dim3(32, 8)>>>(pGM, pA + 256, pB + 256, out);
}